// round 9
// baseline (speedup 1.0000x reference)
#include <cuda_runtime.h>
#include <cstdint>
#include <dlfcn.h>

// ============================================================================
// Steerable pyramid, frequency-domain, M=N=512, B=4, C=3, K=4, S=5.
// OUTPUT = float32 REAL PARTS of each tuple element, concatenated:
//   out0 [12][512][512]     off 0         out1 [12][4][256][256]  off 3145728
//   out2 [12][4][128][128]  off 6291456   out3 [12][4][64][64]    off 7077888
//   out4 [12][4][32][32]    off 7274496   out5 [12][4][16][16]    off 7323648
//   out6 [12][16][16]       off 7335936   total 7339008 floats
//
// Pipeline:
//   1) Forward FFT2 of x (12 images)            -> g_X
//   2) Highpass: X*hp, inverse FFT2 full-res    -> out0 (real part)
//   3) Scale j: fold X*ang*sc[j] + downsample phases into QxQ spectrum
//      (Q=512/2^(j+1)), inverse FFT2 at QxQ     -> out[1+j] (real part)
//   4) Lowpass fold (F=32) -> 16x16 inverse     -> out6 (real part)
//
// Downsample-in-frequency (f=2^m, Q=512/f):
//   w[i]=0.5(z[fi+f/2-1]+z[fi+f/2]) => W'[q]=(1/f)sum_r Z[q+Qr] P[q+Qr],
//   P[k]=e^{+i pi k(f-1)/512} cos(pi k/512); w = IFFT_Q(W').
//   2D: 1/f^2 in fold, 1/Q^2 at final pass (f^2 Q^2 = 512^2).
// ============================================================================

#define MM 512
#define NIMG 12
#define KANG 4
#define PI_F 3.14159265358979323846f

#define XT_CAP ((size_t)NIMG * MM * MM)
#define W_CAP  ((size_t)48 * 256 * 256)
#define OUT_TOTAL ((size_t)7339008)

__device__ float2 g_X[NIMG * MM * MM];
__device__ float2 g_T[NIMG * MM * MM];
__device__ float2 g_W[48 * 256 * 256];

#define BUF_X 0
#define BUF_T 1
#define BUF_W 2

__device__ __forceinline__ float2* devbuf(int sel, size_t& cap) {
    if (sel == BUF_X) { cap = XT_CAP; return g_X; }
    if (sel == BUF_T) { cap = XT_CAP; return g_T; }
    cap = W_CAP; return g_W;
}

__host__ __device__ constexpr int clog2(int n) { return n <= 1 ? 0 : 1 + clog2(n >> 1); }

// ---------------------------------------------------------------------------
// Warp-level in-place radix-2 DIF FFT, length L, one warp per smem row.
// sign=-1 forward, +1 inverse (conjugated twiddles). Ends in natural order.
// ---------------------------------------------------------------------------
template<int L>
__device__ void warp_fft(float2* d, const float2* tw, int lane, int sign) {
    constexpr int LOG = clog2(L);
#pragma unroll
    for (int st = 0; st < LOG; st++) {
        const int h = L >> (1 + st);
        const int twm = 1 << st;
        for (int t = lane; t < (L >> 1); t += 32) {
            int j = t & (h - 1);
            int idx = ((t - j) << 1) + j;
            float2 a = d[idx], b = d[idx + h];
            float2 w = tw[j * twm];
            float wy = (sign > 0) ? -w.y : w.y;
            float2 df = make_float2(a.x - b.x, a.y - b.y);
            d[idx]     = make_float2(a.x + b.x, a.y + b.y);
            d[idx + h] = make_float2(df.x * w.x - df.y * wy, df.x * wy + df.y * w.x);
        }
        __syncwarp();
    }
    for (int i = lane; i < L; i += 32) {
        int j = (int)(__brev((unsigned)i) >> (32 - LOG));
        if (j > i) { float2 t0 = d[i]; d[i] = d[j]; d[j] = t0; }
    }
    __syncwarp();
}

// ---------------------------------------------------------------------------
// One 2D-FFT pass over [batch][L][L]: FFT each row, store TRANSPOSED.
// REAL_OUT: final pass -> writes real part only (float32) to ext buffer.
// 8 rows/block, one warp per row, blockDim=256.
// ---------------------------------------------------------------------------
template<int L, bool REAL_IN, bool REAL_OUT>
__global__ void fft_pass_kernel(int src_sel, const void* ext_in, size_t src_cap,
                                int dst_sel, void* ext_out,
                                size_t dst_base, size_t dst_cap,
                                const float* __restrict__ filt, size_t filt_cap,
                                int sign, float scale) {
    constexpr int RPB = 8;
    __shared__ float2 sm[RPB][L + 1];
    __shared__ float2 tw[L / 2];

    const int tid   = threadIdx.x;
    const int lane  = tid & 31;
    const int w     = tid >> 5;
    const int batch = blockIdx.y;
    const int r0    = blockIdx.x * RPB;
    const int r     = r0 + w;

    for (int i = tid; i < L / 2; i += blockDim.x) {
        float s, c;
        sincosf(-2.0f * PI_F * (float)i / (float)L, &s, &c);
        tw[i] = make_float2(c, s);
    }
    __syncthreads();

    const size_t rowb = ((size_t)batch * L + r) * L;
    if (REAL_IN) {
        const float* in = (const float*)ext_in;
        for (int i = lane; i < L; i += 32) {
            float v = (rowb + i < src_cap) ? in[rowb + i] : 0.0f;
            sm[w][i] = make_float2(v, 0.0f);
        }
    } else {
        size_t scap;
        const float2* base = devbuf(src_sel, scap);
        if (filt) {
            const size_t frow = (size_t)r * L;
            for (int i = lane; i < L; i += 32) {
                float2 v = (rowb + i < scap) ? base[rowb + i] : make_float2(0.f, 0.f);
                float ff = (frow + i < filt_cap) ? filt[frow + i] : 0.0f;
                sm[w][i] = make_float2(v.x * ff, v.y * ff);
            }
        } else {
            for (int i = lane; i < L; i += 32)
                sm[w][i] = (rowb + i < scap) ? base[rowb + i] : make_float2(0.f, 0.f);
        }
    }
    __syncwarp();

    warp_fft<L>(&sm[w][0], tw, lane, sign);
    __syncthreads();

    if (REAL_OUT) {
        float* outf = (float*)ext_out;
        for (int idx = tid; idx < RPB * L; idx += blockDim.x) {
            int rl = idx & (RPB - 1);
            int c  = idx >> 3;
            size_t o = dst_base + ((size_t)batch * L + c) * L + (r0 + rl);
            if (o < dst_cap) outf[o] = sm[rl][c].x * scale;
        }
    } else {
        size_t cap;
        float2* out = devbuf(dst_sel, cap);
        for (int idx = tid; idx < RPB * L; idx += blockDim.x) {
            int rl = idx & (RPB - 1);
            int c  = idx >> 3;
            float2 v = sm[rl][c];
            size_t o = ((size_t)batch * L + c) * L + (r0 + rl);
            if (o < cap) out[o] = make_float2(v.x * scale, v.y * scale);
        }
    }
}

// ---------------------------------------------------------------------------
// Band fold: W[img,k,q1,q2] = (1/F^2) sum_{r1,r2} X*ang[k]*sc_j*P(k1)P(k2)
// ---------------------------------------------------------------------------
template<int F>
__global__ void fold_band_kernel(const float* __restrict__ ang, size_t ang_cap,
                                 const float* __restrict__ sc_j, size_t sc_cap) {
    constexpr int Q = MM / F;
    int idx = blockIdx.x * blockDim.x + threadIdx.x;
    if (idx >= KANG * Q * Q) return;
    const int q2 = idx % Q;
    const int q1 = (idx / Q) % Q;
    const int k  = idx / (Q * Q);
    const size_t ang_off = (size_t)k * MM * MM;

    float2 acc[NIMG];
#pragma unroll
    for (int i = 0; i < NIMG; i++) acc[i] = make_float2(0.f, 0.f);
    const float invf2 = 1.0f / (float)(F * F);
    const float phc = PI_F * (float)(F - 1) / (float)MM;

    for (int r1 = 0; r1 < F; r1++) {
        const int k1 = q1 + Q * r1;
        const float c1 = cosf(PI_F * (float)k1 / (float)MM);
        const float ph1 = phc * (float)k1;
        for (int r2 = 0; r2 < F; r2++) {
            const int k2 = q2 + Q * r2;
            const size_t fidx = (size_t)k1 * MM + k2;
            const float s = (fidx < sc_cap) ? sc_j[fidx] : 0.0f;
            if (s == 0.0f) continue;
            const float a = (ang_off + fidx < ang_cap) ? ang[ang_off + fidx] : 0.0f;
            const float mg = s * a * invf2;
            if (mg == 0.0f) continue;
            const float c2 = cosf(PI_F * (float)k2 / (float)MM);
            float sp, cp;
            sincosf(ph1 + phc * (float)k2, &sp, &cp);
            const float m = mg * c1 * c2;
            const float2 wv = make_float2(m * cp, m * sp);
#pragma unroll
            for (int img = 0; img < NIMG; img++) {
                size_t xo = (size_t)img * (MM * MM) + fidx;
                float2 xv = (xo < XT_CAP) ? g_X[xo] : make_float2(0.f, 0.f);
                acc[img].x += xv.x * wv.x - xv.y * wv.y;
                acc[img].y += xv.x * wv.y + xv.y * wv.x;
            }
        }
    }
#pragma unroll
    for (int img = 0; img < NIMG; img++) {
        size_t o = (((size_t)img * KANG + k) * Q + q1) * Q + q2;
        if (o < W_CAP) g_W[o] = acc[img];
    }
}

__global__ void fold_low_kernel(const float* __restrict__ lp, size_t lp_cap) {
    constexpr int F = 32, Q = 16;
    const int idx = threadIdx.x;
    const int q2 = idx & (Q - 1);
    const int q1 = idx >> 4;

    float2 acc[NIMG];
#pragma unroll
    for (int i = 0; i < NIMG; i++) acc[i] = make_float2(0.f, 0.f);
    const float invf2 = 1.0f / (float)(F * F);
    const float phc = PI_F * (float)(F - 1) / (float)MM;

    for (int r1 = 0; r1 < F; r1++) {
        const int k1 = q1 + Q * r1;
        const float c1 = cosf(PI_F * (float)k1 / (float)MM);
        const float ph1 = phc * (float)k1;
        for (int r2 = 0; r2 < F; r2++) {
            const int k2 = q2 + Q * r2;
            const size_t fidx = (size_t)k1 * MM + k2;
            const float s = (fidx < lp_cap) ? lp[fidx] : 0.0f;
            if (s == 0.0f) continue;
            const float c2 = cosf(PI_F * (float)k2 / (float)MM);
            float sp, cp;
            sincosf(ph1 + phc * (float)k2, &sp, &cp);
            const float m = s * invf2 * c1 * c2;
            const float2 wv = make_float2(m * cp, m * sp);
#pragma unroll
            for (int img = 0; img < NIMG; img++) {
                size_t xo = (size_t)img * (MM * MM) + fidx;
                float2 xv = (xo < XT_CAP) ? g_X[xo] : make_float2(0.f, 0.f);
                acc[img].x += xv.x * wv.x - xv.y * wv.y;
                acc[img].y += xv.x * wv.y + xv.y * wv.x;
            }
        }
    }
#pragma unroll
    for (int img = 0; img < NIMG; img++) {
        size_t o = (size_t)img * (Q * Q) + q1 * Q + q2;
        if (o < W_CAP) g_W[o] = acc[img];
    }
}

// ---------------------------------------------------------------------------
// Host: true byte extent of d_out (query only, no alloc). Capacity in FLOATS.
// ---------------------------------------------------------------------------
typedef int (*cuGetRange_t)(unsigned long long*, size_t*, unsigned long long);
static size_t dout_capacity_f(void* d_out, int out_size) {
    size_t bytes = 0;
    void* h = dlopen("libcuda.so.1", RTLD_NOW | RTLD_GLOBAL);
    if (!h) h = dlopen("libcuda.so", RTLD_NOW | RTLD_GLOBAL);
    if (h) {
        cuGetRange_t f = (cuGetRange_t)dlsym(h, "cuMemGetAddressRange_v2");
        if (!f) f = (cuGetRange_t)dlsym(h, "cuMemGetAddressRange");
        if (f) {
            unsigned long long base = 0; size_t sz = 0;
            if (f(&base, &sz, (unsigned long long)(uintptr_t)d_out) == 0 && sz > 0) {
                unsigned long long off = (unsigned long long)(uintptr_t)d_out - base;
                if (off < sz) bytes = sz - off;
            }
        }
    }
    if (bytes == 0) bytes = (size_t)out_size * 4u;
    size_t cap = bytes / 4u;
    if (cap > OUT_TOTAL) cap = OUT_TOTAL;
    return cap;
}

extern "C" void kernel_launch(void* const* d_in, const int* in_sizes, int n_in,
                              void* d_out, int out_size) {
    const float *x = nullptr, *hp = nullptr, *lp = nullptr, *ang = nullptr, *sc = nullptr;
    size_t xs = 0, hs = 0, ls = 0, as_ = 0, ss = 0;
    for (int i = 0; i < n_in; i++) {
        size_t s = (size_t)in_sizes[i];
        const float* p = (const float*)d_in[i];
        if (s == 3145728u && !x)        { x = p;  xs = s; }
        else if (s == 1048576u && !ang) { ang = p; as_ = s; }
        else if (s == 1310720u && !sc)  { sc = p; ss = s; }
        else if (s == 262144u) { if (!hp) { hp = p; hs = s; } else if (!lp) { lp = p; ls = s; } }
    }
    if (!x  && n_in > 0) { x  = (const float*)d_in[0]; xs  = (size_t)in_sizes[0]; }
    if (!hp && n_in > 1) { hp = (const float*)d_in[1]; hs  = (size_t)in_sizes[1]; }
    if (!lp && n_in > 2) { lp = (const float*)d_in[2]; ls  = (size_t)in_sizes[2]; }
    if (!ang&& n_in > 3) { ang= (const float*)d_in[3]; as_ = (size_t)in_sizes[3]; }
    if (!sc && n_in > 4) { sc = (const float*)d_in[4]; ss  = (size_t)in_sizes[4]; }

    const size_t capf = dout_capacity_f(d_out, out_size);
    const dim3 blk(256);
    const size_t scj = 262144u;

    // 1) Forward FFT2 of x -> g_X
    fft_pass_kernel<512, true , false><<<dim3(64, NIMG), blk>>>(
        0, (const void*)x, xs, BUF_T, nullptr, 0, 0, nullptr, 0, -1, 1.0f);
    fft_pass_kernel<512, false, false><<<dim3(64, NIMG), blk>>>(
        BUF_T, nullptr, 0, BUF_X, nullptr, 0, 0, nullptr, 0, -1, 1.0f);

    // 2) Highpass residual -> out0 (real)
    fft_pass_kernel<512, false, false><<<dim3(64, NIMG), blk>>>(
        BUF_X, nullptr, 0, BUF_T, nullptr, 0, 0, hp, hs, +1, 1.0f);
    fft_pass_kernel<512, false, true ><<<dim3(64, NIMG), blk>>>(
        BUF_T, nullptr, 0, 0, d_out, 0, capf, nullptr, 0, +1, 1.0f / 262144.0f);

    // 3) Bands (batch = 48 = 12 imgs * 4 angles)
    fold_band_kernel<2><<<(KANG*256*256 + 255)/256, blk>>>(ang, as_, sc + 0*scj, ss > 0*scj ? ss - 0*scj : 0);
    fft_pass_kernel<256, false, false><<<dim3(32, 48), blk>>>(
        BUF_W, nullptr, 0, BUF_T, nullptr, 0, 0, nullptr, 0, +1, 1.0f);
    fft_pass_kernel<256, false, true ><<<dim3(32, 48), blk>>>(
        BUF_T, nullptr, 0, 0, d_out, 3145728, capf, nullptr, 0, +1, 1.0f / 65536.0f);

    fold_band_kernel<4><<<(KANG*128*128 + 255)/256, blk>>>(ang, as_, sc + 1*scj, ss > 1*scj ? ss - 1*scj : 0);
    fft_pass_kernel<128, false, false><<<dim3(16, 48), blk>>>(
        BUF_W, nullptr, 0, BUF_T, nullptr, 0, 0, nullptr, 0, +1, 1.0f);
    fft_pass_kernel<128, false, true ><<<dim3(16, 48), blk>>>(
        BUF_T, nullptr, 0, 0, d_out, 6291456, capf, nullptr, 0, +1, 1.0f / 16384.0f);

    fold_band_kernel<8><<<(KANG*64*64 + 255)/256, blk>>>(ang, as_, sc + 2*scj, ss > 2*scj ? ss - 2*scj : 0);
    fft_pass_kernel<64, false, false><<<dim3(8, 48), blk>>>(
        BUF_W, nullptr, 0, BUF_T, nullptr, 0, 0, nullptr, 0, +1, 1.0f);
    fft_pass_kernel<64, false, true ><<<dim3(8, 48), blk>>>(
        BUF_T, nullptr, 0, 0, d_out, 7077888, capf, nullptr, 0, +1, 1.0f / 4096.0f);

    fold_band_kernel<16><<<(KANG*32*32 + 255)/256, blk>>>(ang, as_, sc + 3*scj, ss > 3*scj ? ss - 3*scj : 0);
    fft_pass_kernel<32, false, false><<<dim3(4, 48), blk>>>(
        BUF_W, nullptr, 0, BUF_T, nullptr, 0, 0, nullptr, 0, +1, 1.0f);
    fft_pass_kernel<32, false, true ><<<dim3(4, 48), blk>>>(
        BUF_T, nullptr, 0, 0, d_out, 7274496, capf, nullptr, 0, +1, 1.0f / 1024.0f);

    fold_band_kernel<32><<<(KANG*16*16 + 255)/256, blk>>>(ang, as_, sc + 4*scj, ss > 4*scj ? ss - 4*scj : 0);
    fft_pass_kernel<16, false, false><<<dim3(2, 48), blk>>>(
        BUF_W, nullptr, 0, BUF_T, nullptr, 0, 0, nullptr, 0, +1, 1.0f);
    fft_pass_kernel<16, false, true ><<<dim3(2, 48), blk>>>(
        BUF_T, nullptr, 0, 0, d_out, 7323648, capf, nullptr, 0, +1, 1.0f / 256.0f);

    // 4) Lowpass -> out6 (real)
    fold_low_kernel<<<1, blk>>>(lp, ls);
    fft_pass_kernel<16, false, false><<<dim3(2, NIMG), blk>>>(
        BUF_W, nullptr, 0, BUF_T, nullptr, 0, 0, nullptr, 0, +1, 1.0f);
    fft_pass_kernel<16, false, true ><<<dim3(2, NIMG), blk>>>(
        BUF_T, nullptr, 0, 0, d_out, 7335936, capf, nullptr, 0, +1, 1.0f / 256.0f);
}

// round 10
// speedup vs baseline: 1.0893x; 1.0893x over previous
#include <cuda_runtime.h>
#include <cstdint>
#include <dlfcn.h>

// ============================================================================
// Steerable pyramid, frequency-domain, M=N=512, B=4, C=3, K=4, S=5.
// OUTPUT = float32 REAL PARTS of each tuple element, concatenated (7339008 f32).
//
//   1) Forward FFT2 of x (12 images)            -> g_X
//   2) Highpass: X*hp, inverse FFT2 full-res    -> out0
//   3) Scale j: fold X*ang*sc[j] + downsample phases into QxQ spectrum
//      (Q=512/2^(j+1)), inverse FFT2 at QxQ     -> out[1+j]
//   4) Lowpass fold (F=32) -> 16x16 inverse     -> out6
//
// Downsample-in-frequency (f=2^m, Q=512/f):
//   w[i]=0.5(z[fi+f/2-1]+z[fi+f/2]) => W'[q]=(1/f)sum_r Z[q+Qr] P[q+Qr],
//   P[k]=e^{+i pi k(f-1)/512} cos(pi k/512); w = IFFT_Q(W').
//
// FFT: warp-per-row mixed-radix-4 DIF in shared memory, digit-reversal folded
// into the transposed store (no reversal pass), final radix-2 via float4.
// ============================================================================

#define MM 512
#define NIMG 12
#define KANG 4
#define PI_F 3.14159265358979323846f
#define PADR 2

#define XT_CAP ((size_t)NIMG * MM * MM)
#define W_CAP  ((size_t)48 * 256 * 256)
#define OUT_TOTAL ((size_t)7339008)

__device__ float2 g_X[NIMG * MM * MM];
__device__ float2 g_T[NIMG * MM * MM];
__device__ float2 g_W[48 * 256 * 256];

#define BUF_X 0
#define BUF_T 1
#define BUF_W 2

__device__ __forceinline__ float2* devbuf(int sel, size_t& cap) {
    if (sel == BUF_X) { cap = XT_CAP; return g_X; }
    if (sel == BUF_T) { cap = XT_CAP; return g_T; }
    cap = W_CAP; return g_W;
}

__host__ __device__ constexpr int clog2(int n) { return n <= 1 ? 0 : 1 + clog2(n >> 1); }

// Mixed-radix digit reversal matching the stage order below:
// NS4 radix-4 digits (MSB-first in p -> LSB-first in k), then optional radix-2 bit.
template<int L>
__device__ __forceinline__ int digitrev(int p) {
    constexpr int LOG = clog2(L);
    constexpr int NS4 = LOG >> 1;
    int k = 0;
    int shift = LOG;
#pragma unroll
    for (int s = 0; s < NS4; s++) {
        shift -= 2;
        k |= ((p >> shift) & 3) << (2 * s);
    }
    if (LOG & 1) k |= (p & 1) << (2 * NS4);
    return k;
}

// ---------------------------------------------------------------------------
// Warp-level in-place mixed-radix-4 DIF FFT of length L in shared memory.
// tw[t] = exp(-2*pi*i*t/L), t in [0,L). sign=-1 forward, +1 inverse
// (conjugated twiddles). Output in digit-reversed order (see digitrev).
// ---------------------------------------------------------------------------
template<int L>
__device__ __forceinline__ void warp_fft4(float2* d, const float2* tw, int lane, int sign) {
    constexpr int LOG = clog2(L);
    constexpr int NS4 = LOG >> 1;
    const float s = (sign > 0) ? 1.0f : -1.0f;   // +1 inverse, -1 forward
#pragma unroll
    for (int st = 0; st < NS4; st++) {
        const int m = L >> (2 + 2 * st);
        const int tws = 1 << (2 * st);            // L / (4m)
        for (int t = lane; t < (L >> 2); t += 32) {
            const int j = t & (m - 1);
            const int base = ((t & ~(m - 1)) << 2) + j;
            float2 a = d[base], b = d[base + m], c = d[base + 2 * m], e = d[base + 3 * m];
            float2 acp = make_float2(a.x + c.x, a.y + c.y);
            float2 acm = make_float2(a.x - c.x, a.y - c.y);
            float2 bep = make_float2(b.x + e.x, b.y + e.y);
            float2 bem = make_float2(b.x - e.x, b.y - e.y);
            float2 u0 = make_float2(acp.x + bep.x, acp.y + bep.y);
            float2 u2 = make_float2(acp.x - bep.x, acp.y - bep.y);
            float2 u1 = make_float2(acm.x - s * bem.y, acm.y + s * bem.x);
            float2 u3 = make_float2(acm.x + s * bem.y, acm.y - s * bem.x);
            d[base] = u0;
            if (m == 1) {                          // all twiddles are W^0 = 1
                d[base + 1] = u1;
                d[base + 2] = u2;
                d[base + 3] = u3;
            } else {
                float2 w1 = tw[j * tws];
                float2 w2 = tw[2 * j * tws];
                float2 w3 = tw[3 * j * tws];
                float w1y = (sign > 0) ? -w1.y : w1.y;
                float w2y = (sign > 0) ? -w2.y : w2.y;
                float w3y = (sign > 0) ? -w3.y : w3.y;
                d[base + m]     = make_float2(u1.x * w1.x - u1.y * w1y, u1.x * w1y + u1.y * w1.x);
                d[base + 2 * m] = make_float2(u2.x * w2.x - u2.y * w2y, u2.x * w2y + u2.y * w2.x);
                d[base + 3 * m] = make_float2(u3.x * w3.x - u3.y * w3y, u3.x * w3y + u3.y * w3.x);
            }
        }
        __syncwarp();
    }
    if (LOG & 1) {                                 // final radix-2 on adjacent pairs
        float4* d4 = (float4*)d;
        for (int t = lane; t < (L >> 1); t += 32) {
            float4 v = d4[t];
            d4[t] = make_float4(v.x + v.z, v.y + v.w, v.x - v.z, v.y - v.w);
        }
        __syncwarp();
    }
}

// ---------------------------------------------------------------------------
// One 2D-FFT pass over [batch][L][L]: FFT each row, store TRANSPOSED with the
// digit-reversal folded into the column index (memory ends up natural order).
// REAL_OUT: writes real part (float32) to ext buffer. 8 rows/block, warp/row.
// ---------------------------------------------------------------------------
template<int L, bool REAL_IN, bool REAL_OUT>
__global__ void fft_pass_kernel(int src_sel, const void* ext_in, size_t src_cap,
                                int dst_sel, void* ext_out,
                                size_t dst_base, size_t dst_cap,
                                const float* __restrict__ filt, size_t filt_cap,
                                int sign, float scale) {
    constexpr int RPB = 8;
    __shared__ float2 sm[RPB][L + PADR];
    __shared__ float2 tw[L];

    const int tid   = threadIdx.x;
    const int lane  = tid & 31;
    const int w     = tid >> 5;
    const int batch = blockIdx.y;
    const int r0    = blockIdx.x * RPB;
    const int r     = r0 + w;

    for (int i = tid; i < L; i += blockDim.x) {
        float sn, cs;
        sincosf(-2.0f * PI_F * (float)i / (float)L, &sn, &cs);
        tw[i] = make_float2(cs, sn);
    }
    __syncthreads();

    const size_t rowb = ((size_t)batch * L + r) * L;
    if (REAL_IN) {
        const float* in = (const float*)ext_in;
        for (int i = lane; i < L; i += 32) {
            float v = (rowb + i < src_cap) ? in[rowb + i] : 0.0f;
            sm[w][i] = make_float2(v, 0.0f);
        }
    } else {
        size_t scap;
        const float2* base = devbuf(src_sel, scap);
        if (filt) {
            const size_t frow = (size_t)r * L;
            for (int i = lane; i < L; i += 32) {
                float2 v = base[rowb + i];
                float ff = (frow + i < filt_cap) ? filt[frow + i] : 0.0f;
                sm[w][i] = make_float2(v.x * ff, v.y * ff);
            }
        } else {
            for (int i = lane; i < L; i += 32) sm[w][i] = base[rowb + i];
        }
    }
    __syncwarp();

    warp_fft4<L>(&sm[w][0], tw, lane, sign);
    __syncthreads();

    if (REAL_OUT) {
        float* outf = (float*)ext_out;
        for (int idx = tid; idx < RPB * L; idx += blockDim.x) {
            int rl = idx & (RPB - 1);
            int c  = idx >> 3;
            int kk = digitrev<L>(c);
            size_t o = dst_base + ((size_t)batch * L + kk) * L + (r0 + rl);
            if (o < dst_cap) outf[o] = sm[rl][c].x * scale;
        }
    } else {
        size_t cap;
        float2* out = devbuf(dst_sel, cap);
        for (int idx = tid; idx < RPB * L; idx += blockDim.x) {
            int rl = idx & (RPB - 1);
            int c  = idx >> 3;
            int kk = digitrev<L>(c);
            float2 v = sm[rl][c];
            size_t o = ((size_t)batch * L + kk) * L + (r0 + rl);
            if (o < cap) out[o] = make_float2(v.x * scale, v.y * scale);
        }
    }
}

// ---------------------------------------------------------------------------
// Band fold: W[img,k,q1,q2] = (1/F^2) sum_{r1,r2} X*ang[k]*sc_j*P(k1)P(k2)
// ---------------------------------------------------------------------------
template<int F>
__global__ void fold_band_kernel(const float* __restrict__ ang, size_t ang_cap,
                                 const float* __restrict__ sc_j, size_t sc_cap) {
    constexpr int Q = MM / F;
    int idx = blockIdx.x * blockDim.x + threadIdx.x;
    if (idx >= KANG * Q * Q) return;
    const int q2 = idx % Q;
    const int q1 = (idx / Q) % Q;
    const int k  = idx / (Q * Q);
    const size_t ang_off = (size_t)k * MM * MM;

    float2 acc[NIMG];
#pragma unroll
    for (int i = 0; i < NIMG; i++) acc[i] = make_float2(0.f, 0.f);
    const float invf2 = 1.0f / (float)(F * F);
    const float phc = PI_F * (float)(F - 1) / (float)MM;

    for (int r1 = 0; r1 < F; r1++) {
        const int k1 = q1 + Q * r1;
        const float c1 = cosf(PI_F * (float)k1 / (float)MM);
        const float ph1 = phc * (float)k1;
        for (int r2 = 0; r2 < F; r2++) {
            const int k2 = q2 + Q * r2;
            const size_t fidx = (size_t)k1 * MM + k2;
            const float s = (fidx < sc_cap) ? sc_j[fidx] : 0.0f;
            if (s == 0.0f) continue;
            const float a = (ang_off + fidx < ang_cap) ? ang[ang_off + fidx] : 0.0f;
            const float mg = s * a * invf2;
            if (mg == 0.0f) continue;
            const float c2 = cosf(PI_F * (float)k2 / (float)MM);
            float sp, cp;
            sincosf(ph1 + phc * (float)k2, &sp, &cp);
            const float m = mg * c1 * c2;
            const float2 wv = make_float2(m * cp, m * sp);
#pragma unroll
            for (int img = 0; img < NIMG; img++) {
                float2 xv = g_X[(size_t)img * (MM * MM) + fidx];
                acc[img].x += xv.x * wv.x - xv.y * wv.y;
                acc[img].y += xv.x * wv.y + xv.y * wv.x;
            }
        }
    }
#pragma unroll
    for (int img = 0; img < NIMG; img++) {
        size_t o = (((size_t)img * KANG + k) * Q + q1) * Q + q2;
        if (o < W_CAP) g_W[o] = acc[img];
    }
}

__global__ void fold_low_kernel(const float* __restrict__ lp, size_t lp_cap) {
    constexpr int F = 32, Q = 16;
    const int idx = threadIdx.x;
    const int q2 = idx & (Q - 1);
    const int q1 = idx >> 4;

    float2 acc[NIMG];
#pragma unroll
    for (int i = 0; i < NIMG; i++) acc[i] = make_float2(0.f, 0.f);
    const float invf2 = 1.0f / (float)(F * F);
    const float phc = PI_F * (float)(F - 1) / (float)MM;

    for (int r1 = 0; r1 < F; r1++) {
        const int k1 = q1 + Q * r1;
        const float c1 = cosf(PI_F * (float)k1 / (float)MM);
        const float ph1 = phc * (float)k1;
        for (int r2 = 0; r2 < F; r2++) {
            const int k2 = q2 + Q * r2;
            const size_t fidx = (size_t)k1 * MM + k2;
            const float s = (fidx < lp_cap) ? lp[fidx] : 0.0f;
            if (s == 0.0f) continue;
            const float c2 = cosf(PI_F * (float)k2 / (float)MM);
            float sp, cp;
            sincosf(ph1 + phc * (float)k2, &sp, &cp);
            const float m = s * invf2 * c1 * c2;
            const float2 wv = make_float2(m * cp, m * sp);
#pragma unroll
            for (int img = 0; img < NIMG; img++) {
                float2 xv = g_X[(size_t)img * (MM * MM) + fidx];
                acc[img].x += xv.x * wv.x - xv.y * wv.y;
                acc[img].y += xv.x * wv.y + xv.y * wv.x;
            }
        }
    }
#pragma unroll
    for (int img = 0; img < NIMG; img++) {
        size_t o = (size_t)img * (Q * Q) + q1 * Q + q2;
        if (o < W_CAP) g_W[o] = acc[img];
    }
}

// ---------------------------------------------------------------------------
// Host: true byte extent of d_out (query only, no alloc). Capacity in FLOATS.
// ---------------------------------------------------------------------------
typedef int (*cuGetRange_t)(unsigned long long*, size_t*, unsigned long long);
static size_t dout_capacity_f(void* d_out, int out_size) {
    size_t bytes = 0;
    void* h = dlopen("libcuda.so.1", RTLD_NOW | RTLD_GLOBAL);
    if (!h) h = dlopen("libcuda.so", RTLD_NOW | RTLD_GLOBAL);
    if (h) {
        cuGetRange_t f = (cuGetRange_t)dlsym(h, "cuMemGetAddressRange_v2");
        if (!f) f = (cuGetRange_t)dlsym(h, "cuMemGetAddressRange");
        if (f) {
            unsigned long long base = 0; size_t sz = 0;
            if (f(&base, &sz, (unsigned long long)(uintptr_t)d_out) == 0 && sz > 0) {
                unsigned long long off = (unsigned long long)(uintptr_t)d_out - base;
                if (off < sz) bytes = sz - off;
            }
        }
    }
    if (bytes == 0) bytes = (size_t)out_size * 4u;
    size_t cap = bytes / 4u;
    if (cap > OUT_TOTAL) cap = OUT_TOTAL;
    return cap;
}

extern "C" void kernel_launch(void* const* d_in, const int* in_sizes, int n_in,
                              void* d_out, int out_size) {
    const float *x = nullptr, *hp = nullptr, *lp = nullptr, *ang = nullptr, *sc = nullptr;
    size_t xs = 0, hs = 0, ls = 0, as_ = 0, ss = 0;
    for (int i = 0; i < n_in; i++) {
        size_t s = (size_t)in_sizes[i];
        const float* p = (const float*)d_in[i];
        if (s == 3145728u && !x)        { x = p;  xs = s; }
        else if (s == 1048576u && !ang) { ang = p; as_ = s; }
        else if (s == 1310720u && !sc)  { sc = p; ss = s; }
        else if (s == 262144u) { if (!hp) { hp = p; hs = s; } else if (!lp) { lp = p; ls = s; } }
    }
    if (!x  && n_in > 0) { x  = (const float*)d_in[0]; xs  = (size_t)in_sizes[0]; }
    if (!hp && n_in > 1) { hp = (const float*)d_in[1]; hs  = (size_t)in_sizes[1]; }
    if (!lp && n_in > 2) { lp = (const float*)d_in[2]; ls  = (size_t)in_sizes[2]; }
    if (!ang&& n_in > 3) { ang= (const float*)d_in[3]; as_ = (size_t)in_sizes[3]; }
    if (!sc && n_in > 4) { sc = (const float*)d_in[4]; ss  = (size_t)in_sizes[4]; }

    const size_t capf = dout_capacity_f(d_out, out_size);
    const dim3 blk(256);
    const size_t scj = 262144u;

    // 1) Forward FFT2 of x -> g_X
    fft_pass_kernel<512, true , false><<<dim3(64, NIMG), blk>>>(
        0, (const void*)x, xs, BUF_T, nullptr, 0, 0, nullptr, 0, -1, 1.0f);
    fft_pass_kernel<512, false, false><<<dim3(64, NIMG), blk>>>(
        BUF_T, nullptr, 0, BUF_X, nullptr, 0, 0, nullptr, 0, -1, 1.0f);

    // 2) Highpass residual -> out0 (real)
    fft_pass_kernel<512, false, false><<<dim3(64, NIMG), blk>>>(
        BUF_X, nullptr, 0, BUF_T, nullptr, 0, 0, hp, hs, +1, 1.0f);
    fft_pass_kernel<512, false, true ><<<dim3(64, NIMG), blk>>>(
        BUF_T, nullptr, 0, 0, d_out, 0, capf, nullptr, 0, +1, 1.0f / 262144.0f);

    // 3) Bands (batch = 48 = 12 imgs * 4 angles)
    fold_band_kernel<2><<<(KANG*256*256 + 255)/256, blk>>>(ang, as_, sc + 0*scj, ss > 0*scj ? ss - 0*scj : 0);
    fft_pass_kernel<256, false, false><<<dim3(32, 48), blk>>>(
        BUF_W, nullptr, 0, BUF_T, nullptr, 0, 0, nullptr, 0, +1, 1.0f);
    fft_pass_kernel<256, false, true ><<<dim3(32, 48), blk>>>(
        BUF_T, nullptr, 0, 0, d_out, 3145728, capf, nullptr, 0, +1, 1.0f / 65536.0f);

    fold_band_kernel<4><<<(KANG*128*128 + 255)/256, blk>>>(ang, as_, sc + 1*scj, ss > 1*scj ? ss - 1*scj : 0);
    fft_pass_kernel<128, false, false><<<dim3(16, 48), blk>>>(
        BUF_W, nullptr, 0, BUF_T, nullptr, 0, 0, nullptr, 0, +1, 1.0f);
    fft_pass_kernel<128, false, true ><<<dim3(16, 48), blk>>>(
        BUF_T, nullptr, 0, 0, d_out, 6291456, capf, nullptr, 0, +1, 1.0f / 16384.0f);

    fold_band_kernel<8><<<(KANG*64*64 + 255)/256, blk>>>(ang, as_, sc + 2*scj, ss > 2*scj ? ss - 2*scj : 0);
    fft_pass_kernel<64, false, false><<<dim3(8, 48), blk>>>(
        BUF_W, nullptr, 0, BUF_T, nullptr, 0, 0, nullptr, 0, +1, 1.0f);
    fft_pass_kernel<64, false, true ><<<dim3(8, 48), blk>>>(
        BUF_T, nullptr, 0, 0, d_out, 7077888, capf, nullptr, 0, +1, 1.0f / 4096.0f);

    fold_band_kernel<16><<<(KANG*32*32 + 255)/256, blk>>>(ang, as_, sc + 3*scj, ss > 3*scj ? ss - 3*scj : 0);
    fft_pass_kernel<32, false, false><<<dim3(4, 48), blk>>>(
        BUF_W, nullptr, 0, BUF_T, nullptr, 0, 0, nullptr, 0, +1, 1.0f);
    fft_pass_kernel<32, false, true ><<<dim3(4, 48), blk>>>(
        BUF_T, nullptr, 0, 0, d_out, 7274496, capf, nullptr, 0, +1, 1.0f / 1024.0f);

    fold_band_kernel<32><<<(KANG*16*16 + 255)/256, blk>>>(ang, as_, sc + 4*scj, ss > 4*scj ? ss - 4*scj : 0);
    fft_pass_kernel<16, false, false><<<dim3(2, 48), blk>>>(
        BUF_W, nullptr, 0, BUF_T, nullptr, 0, 0, nullptr, 0, +1, 1.0f);
    fft_pass_kernel<16, false, true ><<<dim3(2, 48), blk>>>(
        BUF_T, nullptr, 0, 0, d_out, 7323648, capf, nullptr, 0, +1, 1.0f / 256.0f);

    // 4) Lowpass -> out6 (real)
    fold_low_kernel<<<1, blk>>>(lp, ls);
    fft_pass_kernel<16, false, false><<<dim3(2, NIMG), blk>>>(
        BUF_W, nullptr, 0, BUF_T, nullptr, 0, 0, nullptr, 0, +1, 1.0f);
    fft_pass_kernel<16, false, true ><<<dim3(2, NIMG), blk>>>(
        BUF_T, nullptr, 0, 0, d_out, 7335936, capf, nullptr, 0, +1, 1.0f / 256.0f);
}

// round 12
// speedup vs baseline: 1.9861x; 1.8233x over previous
#include <cuda_runtime.h>
#include <cstdint>
#include <dlfcn.h>

// ============================================================================
// Steerable pyramid, frequency-domain, M=N=512, B=4, C=3, K=4, S=5.
// OUTPUT = float32 REAL PARTS of each tuple element, concatenated (7339008 f32).
//
// 13 launches, single stream (no stream/event creation — allocation rules):
//   1-2  forward FFT2 of x -> g_X
//   3-4  highpass inverse FFT2 -> out0
//   5    fold_all: all 5 band folds + lowpass fold in ONE launch
//   6-7  j0 (Q=256) two-pass inverse -> out1
//   8-9  j1 (Q=128) two-pass inverse -> out2
//   10   fused ifft2 Q=64  (j2) -> out3     (whole tile in smem)
//   11   fused ifft2 Q=32  (j3) -> out4
//   12   fused ifft2 Q=16  (j4) -> out5
//   13   fused ifft2 Q=16  (low) -> out6
//
// Downsample-in-frequency (f=2^m, Q=512/f):
//   w[i]=0.5(z[fi+f/2-1]+z[fi+f/2]) => W'[q]=(1/f)sum_r Z[q+Qr] P[q+Qr],
//   P[k]=e^{+i pi k(f-1)/512} cos(pi k/512); w = IFFT_Q(W').
//
// FFT: warp-per-row mixed-radix-4 DIF in smem, digit-reversal folded into
// stores. Big passes: RPB=16 (384 blocks -> single wave at 3 blocks/SM).
// ============================================================================

#define MM 512
#define NIMG 12
#define KANG 4
#define PI_F 3.14159265358979323846f
#define PADR 2

#define X_CAP    ((size_t)NIMG * MM * MM)
#define POOL_CAP ((size_t)11532288)
#define OUT_TOTAL ((size_t)7339008)

__device__ float2 g_X[NIMG * MM * MM];
__device__ float2 g_P[11532288];

// Scratch pool layout (float2 offsets)
#define OFF_FT   ((size_t)0)
#define OFF_W0   ((size_t)3145728)
#define OFF_T0   ((size_t)6291456)
#define OFF_W1   ((size_t)9437184)
#define OFF_T1   ((size_t)10223616)
#define OFF_W2   ((size_t)11010048)
#define OFF_W3   ((size_t)11403264)
#define OFF_W4   ((size_t)11501568)
#define OFF_WL   ((size_t)11526144)

__host__ __device__ constexpr int clog2(int n) { return n <= 1 ? 0 : 1 + clog2(n >> 1); }

template<int L>
__device__ __forceinline__ int digitrev(int p) {
    constexpr int LOG = clog2(L);
    constexpr int NS4 = LOG >> 1;
    int k = 0;
    int shift = LOG;
#pragma unroll
    for (int s = 0; s < NS4; s++) {
        shift -= 2;
        k |= ((p >> shift) & 3) << (2 * s);
    }
    if (LOG & 1) k |= (p & 1) << (2 * NS4);
    return k;
}

// ---------------------------------------------------------------------------
// Warp-level in-place mixed-radix-4 DIF FFT of length L (row stride 1).
// tw[t]=exp(-2*pi*i*t/L). sign=-1 fwd, +1 inv. Digit-reversed output order.
// Row base must be 16-byte aligned (float4 final stage).
// ---------------------------------------------------------------------------
template<int L>
__device__ __forceinline__ void warp_fft4(float2* d, const float2* tw, int lane, int sign) {
    constexpr int LOG = clog2(L);
    constexpr int NS4 = LOG >> 1;
    const float s = (sign > 0) ? 1.0f : -1.0f;
#pragma unroll
    for (int st = 0; st < NS4; st++) {
        const int m = L >> (2 + 2 * st);
        const int tws = 1 << (2 * st);
        for (int t = lane; t < (L >> 2); t += 32) {
            const int j = t & (m - 1);
            const int base = ((t & ~(m - 1)) << 2) + j;
            float2 a = d[base], b = d[base + m], c = d[base + 2 * m], e = d[base + 3 * m];
            float2 acp = make_float2(a.x + c.x, a.y + c.y);
            float2 acm = make_float2(a.x - c.x, a.y - c.y);
            float2 bep = make_float2(b.x + e.x, b.y + e.y);
            float2 bem = make_float2(b.x - e.x, b.y - e.y);
            float2 u0 = make_float2(acp.x + bep.x, acp.y + bep.y);
            float2 u2 = make_float2(acp.x - bep.x, acp.y - bep.y);
            float2 u1 = make_float2(acm.x - s * bem.y, acm.y + s * bem.x);
            float2 u3 = make_float2(acm.x + s * bem.y, acm.y - s * bem.x);
            d[base] = u0;
            if (m == 1) {
                d[base + 1] = u1;
                d[base + 2] = u2;
                d[base + 3] = u3;
            } else {
                float2 w1 = tw[j * tws];
                float2 w2 = tw[2 * j * tws];
                float2 w3 = tw[3 * j * tws];
                float w1y = (sign > 0) ? -w1.y : w1.y;
                float w2y = (sign > 0) ? -w2.y : w2.y;
                float w3y = (sign > 0) ? -w3.y : w3.y;
                d[base + m]     = make_float2(u1.x * w1.x - u1.y * w1y, u1.x * w1y + u1.y * w1.x);
                d[base + 2 * m] = make_float2(u2.x * w2.x - u2.y * w2y, u2.x * w2y + u2.y * w2.x);
                d[base + 3 * m] = make_float2(u3.x * w3.x - u3.y * w3y, u3.x * w3y + u3.y * w3.x);
            }
        }
        __syncwarp();
    }
    if (LOG & 1) {
        float4* d4 = (float4*)d;
        for (int t = lane; t < (L >> 1); t += 32) {
            float4 v = d4[t];
            d4[t] = make_float4(v.x + v.z, v.y + v.w, v.x - v.z, v.y - v.w);
        }
        __syncwarp();
    }
}

// ---------------------------------------------------------------------------
// One 2D-FFT pass over [batch][L][L], 16 rows/block (512 threads, warp/row),
// transposed store with digit-reversal folded in. Dynamic smem.
// ---------------------------------------------------------------------------
template<int L, bool REAL_IN, bool REAL_OUT>
__global__ void fft_pass_kernel(const float* __restrict__ ext_in, size_t src_cap,
                                int src_sel, size_t src_off,
                                float* __restrict__ ext_out, size_t dst_base, size_t dst_cap,
                                int dst_sel, size_t dst_off,
                                const float* __restrict__ filt, size_t filt_cap,
                                int sign, float scale) {
    constexpr int RPB = 16;
    extern __shared__ unsigned char dynraw[];
    float2* sm = (float2*)dynraw;                 // [RPB][L+PADR]
    float2* tw = sm + RPB * (L + PADR);           // [L]

    const int tid   = threadIdx.x;
    const int lane  = tid & 31;
    const int w     = tid >> 5;
    const int batch = blockIdx.y;
    const int r0    = blockIdx.x * RPB;
    const int r     = r0 + w;
    float2* row = sm + w * (L + PADR);

    for (int i = tid; i < L; i += blockDim.x) {
        float sn, cs;
        sincosf(-2.0f * PI_F * (float)i / (float)L, &sn, &cs);
        tw[i] = make_float2(cs, sn);
    }
    __syncthreads();

    const size_t rowb = ((size_t)batch * L + r) * L;
    if (REAL_IN) {
        for (int i = lane; i < L; i += 32) {
            float v = (rowb + i < src_cap) ? ext_in[rowb + i] : 0.0f;
            row[i] = make_float2(v, 0.0f);
        }
    } else {
        const float2* base = (src_sel == 0 ? g_X : g_P) + src_off;
        if (filt) {
            const size_t frow = (size_t)r * L;
            for (int i = lane; i < L; i += 32) {
                float2 v = base[rowb + i];
                float ff = (frow + i < filt_cap) ? filt[frow + i] : 0.0f;
                row[i] = make_float2(v.x * ff, v.y * ff);
            }
        } else {
            for (int i = lane; i < L; i += 32) row[i] = base[rowb + i];
        }
    }
    __syncwarp();

    warp_fft4<L>(row, tw, lane, sign);
    __syncthreads();

    if (REAL_OUT) {
        for (int idx = tid; idx < RPB * L; idx += blockDim.x) {
            int rl = idx & (RPB - 1);
            int c  = idx >> 4;
            int kk = digitrev<L>(c);
            size_t o = dst_base + ((size_t)batch * L + kk) * L + (r0 + rl);
            if (o < dst_cap) ext_out[o] = sm[rl * (L + PADR) + c].x * scale;
        }
    } else {
        float2* out = (dst_sel == 0 ? g_X : g_P);
        const size_t cap = (dst_sel == 0 ? X_CAP : POOL_CAP);
        for (int idx = tid; idx < RPB * L; idx += blockDim.x) {
            int rl = idx & (RPB - 1);
            int c  = idx >> 4;
            int kk = digitrev<L>(c);
            float2 v = sm[rl * (L + PADR) + c];
            size_t o = dst_off + ((size_t)batch * L + kk) * L + (r0 + rl);
            if (o < cap) out[o] = make_float2(v.x * scale, v.y * scale);
        }
    }
}

// ---------------------------------------------------------------------------
// Fused small-band inverse FFT2: whole QxQ tile in shared memory.
// Row FFTs -> in-smem transpose (digit-rev corrected) -> row FFTs -> real out.
// One block per batch element. blockDim=256. Dynamic smem = 2*Q*(Q+PADR)*8.
// ---------------------------------------------------------------------------
template<int Q>
__global__ void fused_ifft2_kernel(size_t w_off, float* __restrict__ out,
                                   size_t dst_base, size_t dst_cap, float scale) {
    extern __shared__ unsigned char dynraw[];
    float2* A = (float2*)dynraw;                  // [Q][Q+PADR]
    float2* B = A + Q * (Q + PADR);
    __shared__ float2 tw[Q];
    __shared__ int inv[Q];

    const int tid  = threadIdx.x;
    const int lane = tid & 31;
    const int w    = tid >> 5;
    const int nw   = blockDim.x >> 5;
    const int batch = blockIdx.x;

    for (int i = tid; i < Q; i += blockDim.x) {
        float sn, cs;
        sincosf(-2.0f * PI_F * (float)i / (float)Q, &sn, &cs);
        tw[i] = make_float2(cs, sn);
        inv[digitrev<Q>(i)] = i;                  // freq -> position
    }
    __syncthreads();

    for (int i = tid; i < Q * Q; i += blockDim.x) {
        int r = i / Q, c = i % Q;
        A[r * (Q + PADR) + c] = g_P[w_off + (size_t)batch * Q * Q + i];
    }
    __syncthreads();

    for (int r = w; r < Q; r += nw) warp_fft4<Q>(A + r * (Q + PADR), tw, lane, +1);
    __syncthreads();

    for (int i = tid; i < Q * Q; i += blockDim.x) {
        int r = i / Q, c = i % Q;
        B[digitrev<Q>(c) * (Q + PADR) + r] = A[r * (Q + PADR) + c];
    }
    __syncthreads();

    for (int y = w; y < Q; y += nw) warp_fft4<Q>(B + y * (Q + PADR), tw, lane, +1);
    __syncthreads();

    for (int i = tid; i < Q * Q; i += blockDim.x) {
        int kk2 = i / Q, kk1 = i % Q;
        int c2 = inv[kk2];
        size_t o = dst_base + (size_t)batch * Q * Q + i;
        if (o < dst_cap) out[o] = B[kk1 * (Q + PADR) + c2].x * scale;
    }
}

// ---------------------------------------------------------------------------
// fold_all: all band folds + lowpass fold in ONE launch (block-range dispatch).
//   W[img,k,q1,q2] = (1/F^2) sum_{r1,r2} X*ang[k]*sc_j*P(k1)P(k2)
// ---------------------------------------------------------------------------
__device__ __forceinline__ void fold_body(int F, int Q, int bid0,
                                          const float* __restrict__ ang, size_t ang_cap,
                                          const float* __restrict__ sc_j, size_t sc_cap,
                                          size_t w_off) {
    int idx = (blockIdx.x - bid0) * blockDim.x + threadIdx.x;
    if (idx >= KANG * Q * Q) return;
    const int q2 = idx % Q;
    const int q1 = (idx / Q) % Q;
    const int k  = idx / (Q * Q);
    const size_t ang_off = (size_t)k * MM * MM;

    float2 acc[NIMG];
#pragma unroll
    for (int i = 0; i < NIMG; i++) acc[i] = make_float2(0.f, 0.f);
    const float invf2 = 1.0f / (float)(F * F);
    const float phc = PI_F * (float)(F - 1) / (float)MM;

    for (int r1 = 0; r1 < F; r1++) {
        const int k1 = q1 + Q * r1;
        const float c1 = cosf(PI_F * (float)k1 / (float)MM);
        const float ph1 = phc * (float)k1;
        for (int r2 = 0; r2 < F; r2++) {
            const int k2 = q2 + Q * r2;
            const size_t fidx = (size_t)k1 * MM + k2;
            const float s = (fidx < sc_cap) ? sc_j[fidx] : 0.0f;
            if (s == 0.0f) continue;
            const float a = (ang_off + fidx < ang_cap) ? ang[ang_off + fidx] : 0.0f;
            const float mg = s * a * invf2;
            if (mg == 0.0f) continue;
            const float c2 = cosf(PI_F * (float)k2 / (float)MM);
            float sp, cp;
            sincosf(ph1 + phc * (float)k2, &sp, &cp);
            const float m = mg * c1 * c2;
            const float2 wv = make_float2(m * cp, m * sp);
#pragma unroll
            for (int img = 0; img < NIMG; img++) {
                float2 xv = g_X[(size_t)img * (MM * MM) + fidx];
                acc[img].x += xv.x * wv.x - xv.y * wv.y;
                acc[img].y += xv.x * wv.y + xv.y * wv.x;
            }
        }
    }
#pragma unroll
    for (int img = 0; img < NIMG; img++) {
        size_t o = w_off + (((size_t)img * KANG + k) * Q + q1) * Q + q2;
        if (o < POOL_CAP) g_P[o] = acc[img];
    }
}

__device__ __forceinline__ void fold_low_body(const float* __restrict__ lp, size_t lp_cap,
                                              size_t w_off) {
    constexpr int F = 32, Q = 16;
    const int idx = threadIdx.x;
    const int q2 = idx & (Q - 1);
    const int q1 = idx >> 4;

    float2 acc[NIMG];
#pragma unroll
    for (int i = 0; i < NIMG; i++) acc[i] = make_float2(0.f, 0.f);
    const float invf2 = 1.0f / (float)(F * F);
    const float phc = PI_F * (float)(F - 1) / (float)MM;

    for (int r1 = 0; r1 < F; r1++) {
        const int k1 = q1 + Q * r1;
        const float c1 = cosf(PI_F * (float)k1 / (float)MM);
        const float ph1 = phc * (float)k1;
        for (int r2 = 0; r2 < F; r2++) {
            const int k2 = q2 + Q * r2;
            const size_t fidx = (size_t)k1 * MM + k2;
            const float s = (fidx < lp_cap) ? lp[fidx] : 0.0f;
            if (s == 0.0f) continue;
            const float c2 = cosf(PI_F * (float)k2 / (float)MM);
            float sp, cp;
            sincosf(ph1 + phc * (float)k2, &sp, &cp);
            const float m = s * invf2 * c1 * c2;
            const float2 wv = make_float2(m * cp, m * sp);
#pragma unroll
            for (int img = 0; img < NIMG; img++) {
                float2 xv = g_X[(size_t)img * (MM * MM) + fidx];
                acc[img].x += xv.x * wv.x - xv.y * wv.y;
                acc[img].y += xv.x * wv.y + xv.y * wv.x;
            }
        }
    }
#pragma unroll
    for (int img = 0; img < NIMG; img++) {
        size_t o = w_off + (size_t)img * (Q * Q) + q1 * Q + q2;
        if (o < POOL_CAP) g_P[o] = acc[img];
    }
}

__global__ void fold_all_kernel(const float* __restrict__ ang, size_t ang_cap,
                                const float* __restrict__ sc, size_t sc_cap,
                                const float* __restrict__ lp, size_t lp_cap) {
    const int b = blockIdx.x;
    const size_t scj = 262144u;
    if (b < 1024)
        fold_body(2, 256, 0, ang, ang_cap, sc, sc_cap, OFF_W0);
    else if (b < 1280)
        fold_body(4, 128, 1024, ang, ang_cap, sc + 1 * scj, sc_cap > 1 * scj ? sc_cap - 1 * scj : 0, OFF_W1);
    else if (b < 1344)
        fold_body(8, 64, 1280, ang, ang_cap, sc + 2 * scj, sc_cap > 2 * scj ? sc_cap - 2 * scj : 0, OFF_W2);
    else if (b < 1360)
        fold_body(16, 32, 1344, ang, ang_cap, sc + 3 * scj, sc_cap > 3 * scj ? sc_cap - 3 * scj : 0, OFF_W3);
    else if (b < 1364)
        fold_body(32, 16, 1360, ang, ang_cap, sc + 4 * scj, sc_cap > 4 * scj ? sc_cap - 4 * scj : 0, OFF_W4);
    else
        fold_low_body(lp, lp_cap, OFF_WL);
}

// ---------------------------------------------------------------------------
typedef int (*cuGetRange_t)(unsigned long long*, size_t*, unsigned long long);
static size_t dout_capacity_f(void* d_out, int out_size) {
    size_t bytes = 0;
    void* h = dlopen("libcuda.so.1", RTLD_NOW | RTLD_GLOBAL);
    if (!h) h = dlopen("libcuda.so", RTLD_NOW | RTLD_GLOBAL);
    if (h) {
        cuGetRange_t f = (cuGetRange_t)dlsym(h, "cuMemGetAddressRange_v2");
        if (!f) f = (cuGetRange_t)dlsym(h, "cuMemGetAddressRange");
        if (f) {
            unsigned long long base = 0; size_t sz = 0;
            if (f(&base, &sz, (unsigned long long)(uintptr_t)d_out) == 0 && sz > 0) {
                unsigned long long off = (unsigned long long)(uintptr_t)d_out - base;
                if (off < sz) bytes = sz - off;
            }
        }
    }
    if (bytes == 0) bytes = (size_t)out_size * 4u;
    size_t cap = bytes / 4u;
    if (cap > OUT_TOTAL) cap = OUT_TOTAL;
    return cap;
}

extern "C" void kernel_launch(void* const* d_in, const int* in_sizes, int n_in,
                              void* d_out, int out_size) {
    const float *x = nullptr, *hp = nullptr, *lp = nullptr, *ang = nullptr, *sc = nullptr;
    size_t xs = 0, hs = 0, ls = 0, as_ = 0, ss = 0;
    for (int i = 0; i < n_in; i++) {
        size_t s = (size_t)in_sizes[i];
        const float* p = (const float*)d_in[i];
        if (s == 3145728u && !x)        { x = p;  xs = s; }
        else if (s == 1048576u && !ang) { ang = p; as_ = s; }
        else if (s == 1310720u && !sc)  { sc = p; ss = s; }
        else if (s == 262144u) { if (!hp) { hp = p; hs = s; } else if (!lp) { lp = p; ls = s; } }
    }
    if (!x  && n_in > 0) { x  = (const float*)d_in[0]; xs  = (size_t)in_sizes[0]; }
    if (!hp && n_in > 1) { hp = (const float*)d_in[1]; hs  = (size_t)in_sizes[1]; }
    if (!lp && n_in > 2) { lp = (const float*)d_in[2]; ls  = (size_t)in_sizes[2]; }
    if (!ang&& n_in > 3) { ang= (const float*)d_in[3]; as_ = (size_t)in_sizes[3]; }
    if (!sc && n_in > 4) { sc = (const float*)d_in[4]; ss  = (size_t)in_sizes[4]; }

    float* outf = (float*)d_out;
    const size_t capf = dout_capacity_f(d_out, out_size);

    // dynamic smem sizes
    const int sm512 = (16 * (512 + PADR) + 512) * 8;   // 69888
    const int sm256 = (16 * (256 + PADR) + 256) * 8;   // 35072
    const int sm128 = (16 * (128 + PADR) + 128) * 8;   // 17664
    const int smf64 = 2 * 64 * (64 + PADR) * 8;        // 67584
    const int smf32 = 2 * 32 * (32 + PADR) * 8;        // 17408
    const int smf16 = 2 * 16 * (16 + PADR) * 8;        //  4608

    cudaFuncSetAttribute(fft_pass_kernel<512, true , false>, cudaFuncAttributeMaxDynamicSharedMemorySize, sm512);
    cudaFuncSetAttribute(fft_pass_kernel<512, false, false>, cudaFuncAttributeMaxDynamicSharedMemorySize, sm512);
    cudaFuncSetAttribute(fft_pass_kernel<512, false, true >, cudaFuncAttributeMaxDynamicSharedMemorySize, sm512);
    cudaFuncSetAttribute(fused_ifft2_kernel<64>, cudaFuncAttributeMaxDynamicSharedMemorySize, smf64);

    const dim3 blk(512);
    const dim3 blkF(256);

    // 1) forward FFT2 of x -> g_X
    fft_pass_kernel<512, true , false><<<dim3(32, NIMG), blk, sm512>>>(
        x, xs, 0, 0, nullptr, 0, 0, 1, OFF_FT, nullptr, 0, -1, 1.0f);
    fft_pass_kernel<512, false, false><<<dim3(32, NIMG), blk, sm512>>>(
        nullptr, 0, 1, OFF_FT, nullptr, 0, 0, 0, 0, nullptr, 0, -1, 1.0f);

    // 2) highpass -> out0
    fft_pass_kernel<512, false, false><<<dim3(32, NIMG), blk, sm512>>>(
        nullptr, 0, 0, 0, nullptr, 0, 0, 1, OFF_FT, hp, hs, +1, 1.0f);
    fft_pass_kernel<512, false, true ><<<dim3(32, NIMG), blk, sm512>>>(
        nullptr, 0, 1, OFF_FT, outf, 0, capf, 0, 0, nullptr, 0, +1, 1.0f / 262144.0f);

    // 3) all folds in one launch
    fold_all_kernel<<<1365, blkF>>>(ang, as_, sc, ss, lp, ls);

    // 4) j0 (Q=256) -> out1
    fft_pass_kernel<256, false, false><<<dim3(16, 48), blk, sm256>>>(
        nullptr, 0, 1, OFF_W0, nullptr, 0, 0, 1, OFF_T0, nullptr, 0, +1, 1.0f);
    fft_pass_kernel<256, false, true ><<<dim3(16, 48), blk, sm256>>>(
        nullptr, 0, 1, OFF_T0, outf, 3145728, capf, 0, 0, nullptr, 0, +1, 1.0f / 65536.0f);

    // 5) j1 (Q=128) -> out2
    fft_pass_kernel<128, false, false><<<dim3(8, 48), blk, sm128>>>(
        nullptr, 0, 1, OFF_W1, nullptr, 0, 0, 1, OFF_T1, nullptr, 0, +1, 1.0f);
    fft_pass_kernel<128, false, true ><<<dim3(8, 48), blk, sm128>>>(
        nullptr, 0, 1, OFF_T1, outf, 6291456, capf, 0, 0, nullptr, 0, +1, 1.0f / 16384.0f);

    // 6) fused small bands
    fused_ifft2_kernel<64><<<48, blkF, smf64>>>(OFF_W2, outf, 7077888, capf, 1.0f / 4096.0f);
    fused_ifft2_kernel<32><<<48, blkF, smf32>>>(OFF_W3, outf, 7274496, capf, 1.0f / 1024.0f);
    fused_ifft2_kernel<16><<<48, blkF, smf16>>>(OFF_W4, outf, 7323648, capf, 1.0f / 256.0f);
    fused_ifft2_kernel<16><<<12, blkF, smf16>>>(OFF_WL, outf, 7335936, capf, 1.0f / 256.0f);
}

// round 13
// speedup vs baseline: 2.1400x; 1.0775x over previous
#include <cuda_runtime.h>
#include <cstdint>
#include <dlfcn.h>

// ============================================================================
// Steerable pyramid, frequency-domain, M=N=512, B=4, C=3, K=4, S=5.
// OUTPUT = float32 REAL PARTS of each tuple element, concatenated (7339008 f32).
//
// 13 launches:
//   1-2  forward FFT2 of x -> g_X          (shuffle-FFT passes)
//   3-4  highpass inverse FFT2 -> out0     (shuffle-FFT passes)
//   5    fold_all (all 5 band folds + lowpass fold)
//   6-7  j0 (Q=256) -> out1   8-9  j1 (Q=128) -> out2   (shuffle-FFT passes)
//   10-13 fused ifft2 Q=64/32/16/16 -> out3..6 (smem warp_fft4, small)
//
// Shuffle FFT (L = 32*R): n = R*a + b (lane a, reg b).
//   X[c+32d] = FFT_R over b [ W_L^{bc} * FFT32_lanes(f[R*.+b])(c) ]
//   FFT32 = 5 shfl_xor radix-2 stages (c = brev5(lane)); FFT_R in registers
//   (output reg q <-> d = brev(q)). No smem in butterflies -> no bank
//   conflicts. smem used only to stage the transposed store.
// ============================================================================

#define MM 512
#define NIMG 12
#define KANG 4
#define PI_F 3.14159265358979323846f
#define PADR 2
#define FULLM 0xffffffffu

#define X_CAP    ((size_t)NIMG * MM * MM)
#define POOL_CAP ((size_t)11532288)
#define OUT_TOTAL ((size_t)7339008)

__device__ float2 g_X[NIMG * MM * MM];
__device__ float2 g_P[11532288];

// Scratch pool layout (float2 offsets)
#define OFF_FT   ((size_t)0)
#define OFF_W0   ((size_t)3145728)
#define OFF_T0   ((size_t)6291456)
#define OFF_W1   ((size_t)9437184)
#define OFF_T1   ((size_t)10223616)
#define OFF_W2   ((size_t)11010048)
#define OFF_W3   ((size_t)11403264)
#define OFF_W4   ((size_t)11501568)
#define OFF_WL   ((size_t)11526144)

__host__ __device__ constexpr int clog2(int n) { return n <= 1 ? 0 : 1 + clog2(n >> 1); }

__device__ __forceinline__ float2 cmul(float2 a, float2 b) {
    return make_float2(a.x * b.x - a.y * b.y, a.x * b.y + a.y * b.x);
}

// ============================================================================
// Shuffle-FFT 2D pass: rows of [batch][L][L], one warp per row, store
// TRANSPOSED (natural order; permutations folded into smem staging).
// ============================================================================
template<int R, bool REAL_IN, bool REAL_OUT>
__global__ void sfft_pass_kernel(const float* __restrict__ ext_in, size_t src_cap,
                                 int src_sel, size_t src_off,
                                 float* __restrict__ ext_out, size_t dst_base, size_t dst_cap,
                                 int dst_sel, size_t dst_off,
                                 const float* __restrict__ filt, size_t filt_cap,
                                 int sign, float scale) {
    constexpr int L = 32 * R;
    constexpr int LOG_R = clog2(R);
    constexpr int RPB = 8;
    __shared__ float2 sm[RPB][L + 1];
    __shared__ float2 twR[R];

    const int tid   = threadIdx.x;
    const int lane  = tid & 31;
    const int w     = tid >> 5;
    const int batch = blockIdx.y;
    const int r0    = blockIdx.x * RPB;
    const int r     = r0 + w;
    const float sg  = (sign > 0) ? 1.0f : -1.0f;

    if (tid < R) {
        float s, c;
        sincosf(sg * 2.0f * PI_F * (float)tid / (float)R, &s, &c);
        twR[tid] = make_float2(c, s);
    }

    // per-lane constants (no per-row trig)
    float2 w32;  // e^{sg*2pi*i*(lane&15)/32}
    {
        float s, c;
        sincosf(sg * 2.0f * PI_F * (float)(lane & 15) / 32.0f, &s, &c);
        w32 = make_float2(c, s);
    }
    const int cidx = (int)(__brev((unsigned)lane) >> 27);   // brev5(lane)
    float2 wc;   // e^{sg*2pi*i*cidx/L}
    {
        float s, c;
        sincosf(sg * 2.0f * PI_F * (float)cidx / (float)L, &s, &c);
        wc = make_float2(c, s);
    }
    __syncthreads();   // twR visible

    // ---- load: lane holds f[R*lane + b], b = 0..R-1
    float2 v[R];
    const size_t rowb = ((size_t)batch * L + r) * L;
    if (REAL_IN) {
#pragma unroll
        for (int b = 0; b < R; b++) {
            size_t o = rowb + R * lane + b;
            float val = (o < src_cap) ? ext_in[o] : 0.0f;
            v[b] = make_float2(val, 0.0f);
        }
    } else {
        const float2* base = (src_sel == 0 ? g_X : g_P) + src_off;
        if (filt) {
            const size_t frow = (size_t)r * L + R * lane;
#pragma unroll
            for (int b = 0; b < R; b++) {
                float2 t = base[rowb + R * lane + b];
                float ff = (frow + b < filt_cap) ? filt[frow + b] : 0.0f;
                v[b] = make_float2(t.x * ff, t.y * ff);
            }
        } else {
#pragma unroll
            for (int b = 0; b < R; b++) v[b] = base[rowb + R * lane + b];
        }
    }

    // ---- FFT-32 across lanes (5 shfl_xor radix-2 DIF stages)
#pragma unroll
    for (int st = 0; st < 5; st++) {
        const int h = 16 >> st;
        const int t = (lane & (h - 1)) * (16 / h);
        const float wre = __shfl_sync(FULLM, w32.x, t);
        const float wim = __shfl_sync(FULLM, w32.y, t);
        const bool hi = (lane & h) != 0;
#pragma unroll
        for (int b = 0; b < R; b++) {
            float ox = __shfl_xor_sync(FULLM, v[b].x, h);
            float oy = __shfl_xor_sync(FULLM, v[b].y, h);
            if (hi) {
                float dx = ox - v[b].x, dy = oy - v[b].y;
                v[b] = make_float2(dx * wre - dy * wim, dx * wim + dy * wre);
            } else {
                v[b].x += ox; v[b].y += oy;
            }
        }
    }

    // ---- twiddle W_L^{b*c}
    {
        float2 cur = wc;
#pragma unroll
        for (int b = 1; b < R; b++) {
            v[b] = cmul(v[b], cur);
            if (b + 1 < R) cur = cmul(cur, wc);
        }
    }

    // ---- FFT-R in registers (DIF radix-2, twiddles from twR broadcast)
#pragma unroll
    for (int h2 = R / 2; h2 >= 1; h2 >>= 1) {
#pragma unroll
        for (int g = 0; g < R; g += 2 * h2) {
#pragma unroll
            for (int j = 0; j < h2; j++) {
                float2 lo = v[g + j], hi2 = v[g + j + h2];
                v[g + j] = make_float2(lo.x + hi2.x, lo.y + hi2.y);
                float2 d = make_float2(lo.x - hi2.x, lo.y - hi2.y);
                float2 tw = twR[j * (R / (2 * h2))];
                v[g + j + h2] = cmul(d, tw);
            }
        }
    }

    // ---- stage to smem in NATURAL frequency order: kk = c + 32*brev(q)
#pragma unroll
    for (int q = 0; q < R; q++) {
        int d = (LOG_R > 0) ? (int)(__brev((unsigned)q) >> (32 - LOG_R)) : 0;
        sm[w][cidx + 32 * d] = v[q];
    }
    __syncthreads();

    // ---- transposed store
    if (REAL_OUT) {
        for (int idx = tid; idx < RPB * L; idx += blockDim.x) {
            int rl = idx & (RPB - 1);
            int cc = idx >> 3;
            size_t o = dst_base + ((size_t)batch * L + cc) * L + (r0 + rl);
            if (o < dst_cap) ext_out[o] = sm[rl][cc].x * scale;
        }
    } else {
        float2* out = (dst_sel == 0 ? g_X : g_P);
        const size_t cap = (dst_sel == 0 ? X_CAP : POOL_CAP);
        for (int idx = tid; idx < RPB * L; idx += blockDim.x) {
            int rl = idx & (RPB - 1);
            int cc = idx >> 3;
            float2 t = sm[rl][cc];
            size_t o = dst_off + ((size_t)batch * L + cc) * L + (r0 + rl);
            if (o < cap) out[o] = make_float2(t.x * scale, t.y * scale);
        }
    }
}

// ============================================================================
// smem warp FFT (kept for the small fused kernels only)
// ============================================================================
template<int L>
__device__ __forceinline__ int digitrev(int p) {
    constexpr int LOG = clog2(L);
    constexpr int NS4 = LOG >> 1;
    int k = 0;
    int shift = LOG;
#pragma unroll
    for (int s = 0; s < NS4; s++) {
        shift -= 2;
        k |= ((p >> shift) & 3) << (2 * s);
    }
    if (LOG & 1) k |= (p & 1) << (2 * NS4);
    return k;
}

template<int L>
__device__ __forceinline__ void warp_fft4(float2* d, const float2* tw, int lane, int sign) {
    constexpr int LOG = clog2(L);
    constexpr int NS4 = LOG >> 1;
    const float s = (sign > 0) ? 1.0f : -1.0f;
#pragma unroll
    for (int st = 0; st < NS4; st++) {
        const int m = L >> (2 + 2 * st);
        const int tws = 1 << (2 * st);
        for (int t = lane; t < (L >> 2); t += 32) {
            const int j = t & (m - 1);
            const int base = ((t & ~(m - 1)) << 2) + j;
            float2 a = d[base], b = d[base + m], c = d[base + 2 * m], e = d[base + 3 * m];
            float2 acp = make_float2(a.x + c.x, a.y + c.y);
            float2 acm = make_float2(a.x - c.x, a.y - c.y);
            float2 bep = make_float2(b.x + e.x, b.y + e.y);
            float2 bem = make_float2(b.x - e.x, b.y - e.y);
            float2 u0 = make_float2(acp.x + bep.x, acp.y + bep.y);
            float2 u2 = make_float2(acp.x - bep.x, acp.y - bep.y);
            float2 u1 = make_float2(acm.x - s * bem.y, acm.y + s * bem.x);
            float2 u3 = make_float2(acm.x + s * bem.y, acm.y - s * bem.x);
            d[base] = u0;
            if (m == 1) {
                d[base + 1] = u1;
                d[base + 2] = u2;
                d[base + 3] = u3;
            } else {
                float2 w1 = tw[j * tws];
                float2 w2 = tw[2 * j * tws];
                float2 w3 = tw[3 * j * tws];
                float w1y = (sign > 0) ? -w1.y : w1.y;
                float w2y = (sign > 0) ? -w2.y : w2.y;
                float w3y = (sign > 0) ? -w3.y : w3.y;
                d[base + m]     = make_float2(u1.x * w1.x - u1.y * w1y, u1.x * w1y + u1.y * w1.x);
                d[base + 2 * m] = make_float2(u2.x * w2.x - u2.y * w2y, u2.x * w2y + u2.y * w2.x);
                d[base + 3 * m] = make_float2(u3.x * w3.x - u3.y * w3y, u3.x * w3y + u3.y * w3.x);
            }
        }
        __syncwarp();
    }
    if (LOG & 1) {
        float4* d4 = (float4*)d;
        for (int t = lane; t < (L >> 1); t += 32) {
            float4 v = d4[t];
            d4[t] = make_float4(v.x + v.z, v.y + v.w, v.x - v.z, v.y - v.w);
        }
        __syncwarp();
    }
}

// Fused small-band inverse FFT2 (tile resident in smem), one block per batch.
template<int Q>
__global__ void fused_ifft2_kernel(size_t w_off, float* __restrict__ out,
                                   size_t dst_base, size_t dst_cap, float scale) {
    extern __shared__ unsigned char dynraw[];
    float2* A = (float2*)dynraw;
    float2* B = A + Q * (Q + PADR);
    __shared__ float2 tw[Q];
    __shared__ int inv[Q];

    const int tid  = threadIdx.x;
    const int lane = tid & 31;
    const int w    = tid >> 5;
    const int nw   = blockDim.x >> 5;
    const int batch = blockIdx.x;

    for (int i = tid; i < Q; i += blockDim.x) {
        float sn, cs;
        sincosf(-2.0f * PI_F * (float)i / (float)Q, &sn, &cs);
        tw[i] = make_float2(cs, sn);
        inv[digitrev<Q>(i)] = i;
    }
    __syncthreads();

    for (int i = tid; i < Q * Q; i += blockDim.x) {
        int r = i / Q, c = i % Q;
        A[r * (Q + PADR) + c] = g_P[w_off + (size_t)batch * Q * Q + i];
    }
    __syncthreads();

    for (int r = w; r < Q; r += nw) warp_fft4<Q>(A + r * (Q + PADR), tw, lane, +1);
    __syncthreads();

    for (int i = tid; i < Q * Q; i += blockDim.x) {
        int r = i / Q, c = i % Q;
        B[digitrev<Q>(c) * (Q + PADR) + r] = A[r * (Q + PADR) + c];
    }
    __syncthreads();

    for (int y = w; y < Q; y += nw) warp_fft4<Q>(B + y * (Q + PADR), tw, lane, +1);
    __syncthreads();

    for (int i = tid; i < Q * Q; i += blockDim.x) {
        int kk2 = i / Q, kk1 = i % Q;
        int c2 = inv[kk2];
        size_t o = dst_base + (size_t)batch * Q * Q + i;
        if (o < dst_cap) out[o] = B[kk1 * (Q + PADR) + c2].x * scale;
    }
}

// ============================================================================
// fold_all: all band folds + lowpass fold in ONE launch.
// ============================================================================
__device__ __forceinline__ void fold_body(int F, int Q, int bid0,
                                          const float* __restrict__ ang, size_t ang_cap,
                                          const float* __restrict__ sc_j, size_t sc_cap,
                                          size_t w_off) {
    int idx = (blockIdx.x - bid0) * blockDim.x + threadIdx.x;
    if (idx >= KANG * Q * Q) return;
    const int q2 = idx % Q;
    const int q1 = (idx / Q) % Q;
    const int k  = idx / (Q * Q);
    const size_t ang_off = (size_t)k * MM * MM;

    float2 acc[NIMG];
#pragma unroll
    for (int i = 0; i < NIMG; i++) acc[i] = make_float2(0.f, 0.f);
    const float invf2 = 1.0f / (float)(F * F);
    const float phc = PI_F * (float)(F - 1) / (float)MM;

    for (int r1 = 0; r1 < F; r1++) {
        const int k1 = q1 + Q * r1;
        const float c1 = cosf(PI_F * (float)k1 / (float)MM);
        const float ph1 = phc * (float)k1;
        for (int r2 = 0; r2 < F; r2++) {
            const int k2 = q2 + Q * r2;
            const size_t fidx = (size_t)k1 * MM + k2;
            const float s = (fidx < sc_cap) ? sc_j[fidx] : 0.0f;
            if (s == 0.0f) continue;
            const float a = (ang_off + fidx < ang_cap) ? ang[ang_off + fidx] : 0.0f;
            const float mg = s * a * invf2;
            if (mg == 0.0f) continue;
            const float c2 = cosf(PI_F * (float)k2 / (float)MM);
            float sp, cp;
            sincosf(ph1 + phc * (float)k2, &sp, &cp);
            const float m = mg * c1 * c2;
            const float2 wv = make_float2(m * cp, m * sp);
#pragma unroll
            for (int img = 0; img < NIMG; img++) {
                float2 xv = g_X[(size_t)img * (MM * MM) + fidx];
                acc[img].x += xv.x * wv.x - xv.y * wv.y;
                acc[img].y += xv.x * wv.y + xv.y * wv.x;
            }
        }
    }
#pragma unroll
    for (int img = 0; img < NIMG; img++) {
        size_t o = w_off + (((size_t)img * KANG + k) * Q + q1) * Q + q2;
        if (o < POOL_CAP) g_P[o] = acc[img];
    }
}

__device__ __forceinline__ void fold_low_body(const float* __restrict__ lp, size_t lp_cap,
                                              size_t w_off) {
    constexpr int F = 32, Q = 16;
    const int idx = threadIdx.x;
    const int q2 = idx & (Q - 1);
    const int q1 = idx >> 4;

    float2 acc[NIMG];
#pragma unroll
    for (int i = 0; i < NIMG; i++) acc[i] = make_float2(0.f, 0.f);
    const float invf2 = 1.0f / (float)(F * F);
    const float phc = PI_F * (float)(F - 1) / (float)MM;

    for (int r1 = 0; r1 < F; r1++) {
        const int k1 = q1 + Q * r1;
        const float c1 = cosf(PI_F * (float)k1 / (float)MM);
        const float ph1 = phc * (float)k1;
        for (int r2 = 0; r2 < F; r2++) {
            const int k2 = q2 + Q * r2;
            const size_t fidx = (size_t)k1 * MM + k2;
            const float s = (fidx < lp_cap) ? lp[fidx] : 0.0f;
            if (s == 0.0f) continue;
            const float c2 = cosf(PI_F * (float)k2 / (float)MM);
            float sp, cp;
            sincosf(ph1 + phc * (float)k2, &sp, &cp);
            const float m = s * invf2 * c1 * c2;
            const float2 wv = make_float2(m * cp, m * sp);
#pragma unroll
            for (int img = 0; img < NIMG; img++) {
                float2 xv = g_X[(size_t)img * (MM * MM) + fidx];
                acc[img].x += xv.x * wv.x - xv.y * wv.y;
                acc[img].y += xv.x * wv.y + xv.y * wv.x;
            }
        }
    }
#pragma unroll
    for (int img = 0; img < NIMG; img++) {
        size_t o = w_off + (size_t)img * (Q * Q) + q1 * Q + q2;
        if (o < POOL_CAP) g_P[o] = acc[img];
    }
}

__global__ void fold_all_kernel(const float* __restrict__ ang, size_t ang_cap,
                                const float* __restrict__ sc, size_t sc_cap,
                                const float* __restrict__ lp, size_t lp_cap) {
    const int b = blockIdx.x;
    const size_t scj = 262144u;
    if (b < 1024)
        fold_body(2, 256, 0, ang, ang_cap, sc, sc_cap, OFF_W0);
    else if (b < 1280)
        fold_body(4, 128, 1024, ang, ang_cap, sc + 1 * scj, sc_cap > 1 * scj ? sc_cap - 1 * scj : 0, OFF_W1);
    else if (b < 1344)
        fold_body(8, 64, 1280, ang, ang_cap, sc + 2 * scj, sc_cap > 2 * scj ? sc_cap - 2 * scj : 0, OFF_W2);
    else if (b < 1360)
        fold_body(16, 32, 1344, ang, ang_cap, sc + 3 * scj, sc_cap > 3 * scj ? sc_cap - 3 * scj : 0, OFF_W3);
    else if (b < 1364)
        fold_body(32, 16, 1360, ang, ang_cap, sc + 4 * scj, sc_cap > 4 * scj ? sc_cap - 4 * scj : 0, OFF_W4);
    else
        fold_low_body(lp, lp_cap, OFF_WL);
}

// ---------------------------------------------------------------------------
typedef int (*cuGetRange_t)(unsigned long long*, size_t*, unsigned long long);
static size_t dout_capacity_f(void* d_out, int out_size) {
    size_t bytes = 0;
    void* h = dlopen("libcuda.so.1", RTLD_NOW | RTLD_GLOBAL);
    if (!h) h = dlopen("libcuda.so", RTLD_NOW | RTLD_GLOBAL);
    if (h) {
        cuGetRange_t f = (cuGetRange_t)dlsym(h, "cuMemGetAddressRange_v2");
        if (!f) f = (cuGetRange_t)dlsym(h, "cuMemGetAddressRange");
        if (f) {
            unsigned long long base = 0; size_t sz = 0;
            if (f(&base, &sz, (unsigned long long)(uintptr_t)d_out) == 0 && sz > 0) {
                unsigned long long off = (unsigned long long)(uintptr_t)d_out - base;
                if (off < sz) bytes = sz - off;
            }
        }
    }
    if (bytes == 0) bytes = (size_t)out_size * 4u;
    size_t cap = bytes / 4u;
    if (cap > OUT_TOTAL) cap = OUT_TOTAL;
    return cap;
}

extern "C" void kernel_launch(void* const* d_in, const int* in_sizes, int n_in,
                              void* d_out, int out_size) {
    const float *x = nullptr, *hp = nullptr, *lp = nullptr, *ang = nullptr, *sc = nullptr;
    size_t xs = 0, hs = 0, ls = 0, as_ = 0, ss = 0;
    for (int i = 0; i < n_in; i++) {
        size_t s = (size_t)in_sizes[i];
        const float* p = (const float*)d_in[i];
        if (s == 3145728u && !x)        { x = p;  xs = s; }
        else if (s == 1048576u && !ang) { ang = p; as_ = s; }
        else if (s == 1310720u && !sc)  { sc = p; ss = s; }
        else if (s == 262144u) { if (!hp) { hp = p; hs = s; } else if (!lp) { lp = p; ls = s; } }
    }
    if (!x  && n_in > 0) { x  = (const float*)d_in[0]; xs  = (size_t)in_sizes[0]; }
    if (!hp && n_in > 1) { hp = (const float*)d_in[1]; hs  = (size_t)in_sizes[1]; }
    if (!lp && n_in > 2) { lp = (const float*)d_in[2]; ls  = (size_t)in_sizes[2]; }
    if (!ang&& n_in > 3) { ang= (const float*)d_in[3]; as_ = (size_t)in_sizes[3]; }
    if (!sc && n_in > 4) { sc = (const float*)d_in[4]; ss  = (size_t)in_sizes[4]; }

    float* outf = (float*)d_out;
    const size_t capf = dout_capacity_f(d_out, out_size);

    const int smf64 = 2 * 64 * (64 + PADR) * 8;
    const int smf32 = 2 * 32 * (32 + PADR) * 8;
    const int smf16 = 2 * 16 * (16 + PADR) * 8;
    cudaFuncSetAttribute(fused_ifft2_kernel<64>, cudaFuncAttributeMaxDynamicSharedMemorySize, smf64);

    const dim3 blk(256);

    // 1) forward FFT2 of x -> g_X  (R=16: L=512)
    sfft_pass_kernel<16, true , false><<<dim3(64, NIMG), blk>>>(
        x, xs, 0, 0, nullptr, 0, 0, 1, OFF_FT, nullptr, 0, -1, 1.0f);
    sfft_pass_kernel<16, false, false><<<dim3(64, NIMG), blk>>>(
        nullptr, 0, 1, OFF_FT, nullptr, 0, 0, 0, 0, nullptr, 0, -1, 1.0f);

    // 2) highpass -> out0
    sfft_pass_kernel<16, false, false><<<dim3(64, NIMG), blk>>>(
        nullptr, 0, 0, 0, nullptr, 0, 0, 1, OFF_FT, hp, hs, +1, 1.0f);
    sfft_pass_kernel<16, false, true ><<<dim3(64, NIMG), blk>>>(
        nullptr, 0, 1, OFF_FT, outf, 0, capf, 0, 0, nullptr, 0, +1, 1.0f / 262144.0f);

    // 3) all folds in one launch
    fold_all_kernel<<<1365, blk>>>(ang, as_, sc, ss, lp, ls);

    // 4) j0 (Q=256, R=8) -> out1
    sfft_pass_kernel<8, false, false><<<dim3(32, 48), blk>>>(
        nullptr, 0, 1, OFF_W0, nullptr, 0, 0, 1, OFF_T0, nullptr, 0, +1, 1.0f);
    sfft_pass_kernel<8, false, true ><<<dim3(32, 48), blk>>>(
        nullptr, 0, 1, OFF_T0, outf, 3145728, capf, 0, 0, nullptr, 0, +1, 1.0f / 65536.0f);

    // 5) j1 (Q=128, R=4) -> out2
    sfft_pass_kernel<4, false, false><<<dim3(16, 48), blk>>>(
        nullptr, 0, 1, OFF_W1, nullptr, 0, 0, 1, OFF_T1, nullptr, 0, +1, 1.0f);
    sfft_pass_kernel<4, false, true ><<<dim3(16, 48), blk>>>(
        nullptr, 0, 1, OFF_T1, outf, 6291456, capf, 0, 0, nullptr, 0, +1, 1.0f / 16384.0f);

    // 6) fused small bands
    fused_ifft2_kernel<64><<<48, blk, smf64>>>(OFF_W2, outf, 7077888, capf, 1.0f / 4096.0f);
    fused_ifft2_kernel<32><<<48, blk, smf32>>>(OFF_W3, outf, 7274496, capf, 1.0f / 1024.0f);
    fused_ifft2_kernel<16><<<48, blk, smf16>>>(OFF_W4, outf, 7323648, capf, 1.0f / 256.0f);
    fused_ifft2_kernel<16><<<12, blk, smf16>>>(OFF_WL, outf, 7335936, capf, 1.0f / 256.0f);
}

// round 14
// speedup vs baseline: 2.3473x; 1.0969x over previous
#include <cuda_runtime.h>
#include <cstdint>
#include <dlfcn.h>

// ============================================================================
// Steerable pyramid, frequency-domain, M=N=512, B=4, C=3, K=4, S=5.
// OUTPUT = float32 REAL PARTS of each tuple element, concatenated (7339008 f32).
//
// 10 launches:
//   1-2  forward FFT2 of x -> g_X          (DIT shuffle-FFT passes)
//   3-4  highpass inverse FFT2 -> out0
//   5    fold_all (all 5 band folds + lowpass fold)
//   6-7  j0 (Q=256) -> out1   8-9  j1 (Q=128) -> out2
//   10   fused_all: ifft2 Q=64/32/16/16 -> out3..6 in ONE launch
//
// DIT shuffle FFT (L = 32*R): n = lane + 32*b  -> COALESCED loads.
//   X[R*k1+k2] = SUM_lane e^{sg 2pi i lane k1/32} [ e^{sg 2pi i lane k2/L}
//                  * FFT_R_regs(f[lane+32b])(k2) ]
//   register FFT_R (DIF, bit-rev k2) -> per-lane twiddle chain ->
//   5-stage shfl_xor FFT32 (bit-rev k1). Staging smem XOR-swizzled
//   (col ^ ((col>>4)&(R-1)) => <=2-way conflicts). CHUNKS loop => 384-block
//   grids = single wave.
// ============================================================================

#define MM 512
#define NIMG 12
#define KANG 4
#define PI_F 3.14159265358979323846f
#define PADR 2
#define FULLM 0xffffffffu

#define X_CAP    ((size_t)NIMG * MM * MM)
#define POOL_CAP ((size_t)11532288)
#define OUT_TOTAL ((size_t)7339008)

__device__ float2 g_X[NIMG * MM * MM];
__device__ float2 g_P[11532288];

#define OFF_FT   ((size_t)0)
#define OFF_W0   ((size_t)3145728)
#define OFF_T0   ((size_t)6291456)
#define OFF_W1   ((size_t)9437184)
#define OFF_T1   ((size_t)10223616)
#define OFF_W2   ((size_t)11010048)
#define OFF_W3   ((size_t)11403264)
#define OFF_W4   ((size_t)11501568)
#define OFF_WL   ((size_t)11526144)

__host__ __device__ constexpr int clog2(int n) { return n <= 1 ? 0 : 1 + clog2(n >> 1); }
__host__ __device__ constexpr int brevc(int x, int bits) {
    int r = 0;
    for (int i = 0; i < bits; i++) r = (r << 1) | ((x >> i) & 1);
    return r;
}

__device__ __forceinline__ float2 cmul(float2 a, float2 b) {
    return make_float2(a.x * b.x - a.y * b.y, a.x * b.y + a.y * b.x);
}

// ============================================================================
// DIT shuffle-FFT 2D pass: rows of [batch][L][L], one warp per row, store
// TRANSPOSED in natural order. CHUNKS row-groups per block.
// ============================================================================
template<int R, int CHUNKS, bool REAL_IN, bool REAL_OUT>
__global__ void sfft_pass_kernel(const float* __restrict__ ext_in, size_t src_cap,
                                 int src_sel, size_t src_off,
                                 float* __restrict__ ext_out, size_t dst_base, size_t dst_cap,
                                 int dst_sel, size_t dst_off,
                                 const float* __restrict__ filt, size_t filt_cap,
                                 int sign, float scale) {
    constexpr int L = 32 * R;
    constexpr int LOG_R = clog2(R);
    constexpr int RPB = 8;
    __shared__ float2 sm[RPB][L + 1];
    __shared__ float2 twR[R];

    const int tid   = threadIdx.x;
    const int lane  = tid & 31;
    const int w     = tid >> 5;
    const int batch = blockIdx.y;
    const float sg  = (sign > 0) ? 1.0f : -1.0f;

    if (tid < R) {
        float s, c;
        sincosf(sg * 2.0f * PI_F * (float)tid / (float)R, &s, &c);
        twR[tid] = make_float2(c, s);
    }
    // per-lane constants
    float2 w32;   // e^{sg 2pi i (lane&15)/32}
    {
        float s, c;
        sincosf(sg * 2.0f * PI_F * (float)(lane & 15) / 32.0f, &s, &c);
        w32 = make_float2(c, s);
    }
    float2 wl;    // e^{sg 2pi i lane / L}
    {
        float s, c;
        sincosf(sg * 2.0f * PI_F * (float)lane / (float)L, &s, &c);
        wl = make_float2(c, s);
    }
    const int b5 = (int)(__brev((unsigned)lane) >> 27);
    __syncthreads();

    for (int ch = 0; ch < CHUNKS; ch++) {
        const int r0 = (blockIdx.x * CHUNKS + ch) * RPB;
        const int r  = r0 + w;
        const size_t rowb = ((size_t)batch * L + r) * L;

        // ---- coalesced load: lane holds f[lane + 32*b]
        float2 v[R];
        if (REAL_IN) {
#pragma unroll
            for (int b = 0; b < R; b++) {
                size_t o = rowb + lane + 32 * b;
                float val = (o < src_cap) ? ext_in[o] : 0.0f;
                v[b] = make_float2(val, 0.0f);
            }
        } else {
            const float2* base = (src_sel == 0 ? g_X : g_P) + src_off;
            if (filt) {
                const size_t frow = (size_t)r * L + lane;
#pragma unroll
                for (int b = 0; b < R; b++) {
                    float2 t = base[rowb + lane + 32 * b];
                    float ff = (frow + 32 * b < filt_cap) ? filt[frow + 32 * b] : 0.0f;
                    v[b] = make_float2(t.x * ff, t.y * ff);
                }
            } else {
#pragma unroll
                for (int b = 0; b < R; b++) v[b] = base[rowb + lane + 32 * b];
            }
        }

        // ---- register FFT_R over b (DIF; reg q holds k2 = brevc(q))
#pragma unroll
        for (int h2 = R / 2; h2 >= 1; h2 >>= 1) {
#pragma unroll
            for (int g = 0; g < R; g += 2 * h2) {
#pragma unroll
                for (int j = 0; j < h2; j++) {
                    float2 lo = v[g + j], hi2 = v[g + j + h2];
                    v[g + j] = make_float2(lo.x + hi2.x, lo.y + hi2.y);
                    float2 d = make_float2(lo.x - hi2.x, lo.y - hi2.y);
                    v[g + j + h2] = cmul(d, twR[j * (R / (2 * h2))]);
                }
            }
        }

        // ---- twiddle: v[q] *= wl^{k2}, k2 = brevc(q)  (chain in k2-order)
        {
            float2 cur = wl;
#pragma unroll
            for (int k2 = 1; k2 < R; k2++) {
                if (k2 > 1) cur = cmul(cur, wl);
                constexpr_fold:;
                const int qq = brevc(k2, LOG_R);
                v[qq] = cmul(v[qq], cur);
            }
        }

        // ---- FFT32 across lanes (5 shfl_xor DIF stages; lane c -> k1=brev5(c))
#pragma unroll
        for (int st = 0; st < 5; st++) {
            const int h = 16 >> st;
            const int t = (lane & (h - 1)) * (16 / h);
            const float wre = __shfl_sync(FULLM, w32.x, t);
            const float wim = __shfl_sync(FULLM, w32.y, t);
            const bool hi = (lane & h) != 0;
#pragma unroll
            for (int b = 0; b < R; b++) {
                float ox = __shfl_xor_sync(FULLM, v[b].x, h);
                float oy = __shfl_xor_sync(FULLM, v[b].y, h);
                if (hi) {
                    float dx = ox - v[b].x, dy = oy - v[b].y;
                    v[b] = make_float2(dx * wre - dy * wim, dx * wim + dy * wre);
                } else {
                    v[b].x += ox; v[b].y += oy;
                }
            }
        }

        // ---- stage to smem, natural order, XOR swizzle
#pragma unroll
        for (int q = 0; q < R; q++) {
            const int col = R * b5 + brevc(q, LOG_R);
            const int ph = col ^ ((col >> 4) & (R - 1));
            sm[w][ph] = v[q];
        }
        __syncthreads();

        // ---- transposed store
        if (REAL_OUT) {
            for (int idx = tid; idx < RPB * L; idx += blockDim.x) {
                int rl = idx & (RPB - 1);
                int cc = idx >> 3;
                int ph = cc ^ ((cc >> 4) & (R - 1));
                size_t o = dst_base + ((size_t)batch * L + cc) * L + (r0 + rl);
                if (o < dst_cap) ext_out[o] = sm[rl][ph].x * scale;
            }
        } else {
            float2* out = (dst_sel == 0 ? g_X : g_P);
            const size_t cap = (dst_sel == 0 ? X_CAP : POOL_CAP);
            for (int idx = tid; idx < RPB * L; idx += blockDim.x) {
                int rl = idx & (RPB - 1);
                int cc = idx >> 3;
                int ph = cc ^ ((cc >> 4) & (R - 1));
                float2 t = sm[rl][ph];
                size_t o = dst_off + ((size_t)batch * L + cc) * L + (r0 + rl);
                if (o < cap) out[o] = make_float2(t.x * scale, t.y * scale);
            }
        }
        __syncthreads();
    }
}

// ============================================================================
// smem warp FFT for the fused small-band kernels
// ============================================================================
template<int L>
__device__ __forceinline__ int digitrev(int p) {
    constexpr int LOG = clog2(L);
    constexpr int NS4 = LOG >> 1;
    int k = 0;
    int shift = LOG;
#pragma unroll
    for (int s = 0; s < NS4; s++) {
        shift -= 2;
        k |= ((p >> shift) & 3) << (2 * s);
    }
    if (LOG & 1) k |= (p & 1) << (2 * NS4);
    return k;
}

template<int L>
__device__ __forceinline__ void warp_fft4(float2* d, const float2* tw, int lane, int sign) {
    constexpr int LOG = clog2(L);
    constexpr int NS4 = LOG >> 1;
    const float s = (sign > 0) ? 1.0f : -1.0f;
#pragma unroll
    for (int st = 0; st < NS4; st++) {
        const int m = L >> (2 + 2 * st);
        const int tws = 1 << (2 * st);
        for (int t = lane; t < (L >> 2); t += 32) {
            const int j = t & (m - 1);
            const int base = ((t & ~(m - 1)) << 2) + j;
            float2 a = d[base], b = d[base + m], c = d[base + 2 * m], e = d[base + 3 * m];
            float2 acp = make_float2(a.x + c.x, a.y + c.y);
            float2 acm = make_float2(a.x - c.x, a.y - c.y);
            float2 bep = make_float2(b.x + e.x, b.y + e.y);
            float2 bem = make_float2(b.x - e.x, b.y - e.y);
            float2 u0 = make_float2(acp.x + bep.x, acp.y + bep.y);
            float2 u2 = make_float2(acp.x - bep.x, acp.y - bep.y);
            float2 u1 = make_float2(acm.x - s * bem.y, acm.y + s * bem.x);
            float2 u3 = make_float2(acm.x + s * bem.y, acm.y - s * bem.x);
            d[base] = u0;
            if (m == 1) {
                d[base + 1] = u1;
                d[base + 2] = u2;
                d[base + 3] = u3;
            } else {
                float2 w1 = tw[j * tws];
                float2 w2 = tw[2 * j * tws];
                float2 w3 = tw[3 * j * tws];
                float w1y = (sign > 0) ? -w1.y : w1.y;
                float w2y = (sign > 0) ? -w2.y : w2.y;
                float w3y = (sign > 0) ? -w3.y : w3.y;
                d[base + m]     = make_float2(u1.x * w1.x - u1.y * w1y, u1.x * w1y + u1.y * w1.x);
                d[base + 2 * m] = make_float2(u2.x * w2.x - u2.y * w2y, u2.x * w2y + u2.y * w2.x);
                d[base + 3 * m] = make_float2(u3.x * w3.x - u3.y * w3y, u3.x * w3y + u3.y * w3.x);
            }
        }
        __syncwarp();
    }
    if (LOG & 1) {
        float4* d4 = (float4*)d;
        for (int t = lane; t < (L >> 1); t += 32) {
            float4 v = d4[t];
            d4[t] = make_float4(v.x + v.z, v.y + v.w, v.x - v.z, v.y - v.w);
        }
        __syncwarp();
    }
}

// Fused small-band inverse FFT2 body (tile resident in smem).
template<int Q>
__device__ void fused_body(void* dynraw, float2* twbuf, int* invbuf,
                           size_t w_off, int batch, float* __restrict__ out,
                           size_t dst_base, size_t dst_cap, float scale) {
    float2* A = (float2*)dynraw;
    float2* B = A + Q * (Q + PADR);

    const int tid  = threadIdx.x;
    const int lane = tid & 31;
    const int w    = tid >> 5;
    const int nw   = blockDim.x >> 5;

    for (int i = tid; i < Q; i += blockDim.x) {
        float sn, cs;
        sincosf(-2.0f * PI_F * (float)i / (float)Q, &sn, &cs);
        twbuf[i] = make_float2(cs, sn);
        invbuf[digitrev<Q>(i)] = i;
    }
    __syncthreads();

    for (int i = tid; i < Q * Q; i += blockDim.x) {
        int r = i / Q, c = i % Q;
        A[r * (Q + PADR) + c] = g_P[w_off + (size_t)batch * Q * Q + i];
    }
    __syncthreads();

    for (int r = w; r < Q; r += nw) warp_fft4<Q>(A + r * (Q + PADR), twbuf, lane, +1);
    __syncthreads();

    for (int i = tid; i < Q * Q; i += blockDim.x) {
        int r = i / Q, c = i % Q;
        B[digitrev<Q>(c) * (Q + PADR) + r] = A[r * (Q + PADR) + c];
    }
    __syncthreads();

    for (int y = w; y < Q; y += nw) warp_fft4<Q>(B + y * (Q + PADR), twbuf, lane, +1);
    __syncthreads();

    for (int i = tid; i < Q * Q; i += blockDim.x) {
        int kk2 = i / Q, kk1 = i % Q;
        int c2 = invbuf[kk2];
        size_t o = dst_base + (size_t)batch * Q * Q + i;
        if (o < dst_cap) out[o] = B[kk1 * (Q + PADR) + c2].x * scale;
    }
}

// All four small-band inverse FFT2s in one launch (156 blocks).
__global__ void fused_all_kernel(float* __restrict__ out, size_t dst_cap) {
    extern __shared__ unsigned char dynraw[];
    __shared__ float2 twbuf[64];
    __shared__ int invbuf[64];
    const int b = blockIdx.x;
    if (b < 48)
        fused_body<64>(dynraw, twbuf, invbuf, OFF_W2, b, out, 7077888, dst_cap, 1.0f / 4096.0f);
    else if (b < 96)
        fused_body<32>(dynraw, twbuf, invbuf, OFF_W3, b - 48, out, 7274496, dst_cap, 1.0f / 1024.0f);
    else if (b < 144)
        fused_body<16>(dynraw, twbuf, invbuf, OFF_W4, b - 96, out, 7323648, dst_cap, 1.0f / 256.0f);
    else
        fused_body<16>(dynraw, twbuf, invbuf, OFF_WL, b - 144, out, 7335936, dst_cap, 1.0f / 256.0f);
}

// ============================================================================
// fold_all: all band folds + lowpass fold in ONE launch.
// ============================================================================
__device__ __forceinline__ void fold_body(int F, int Q, int bid0,
                                          const float* __restrict__ ang, size_t ang_cap,
                                          const float* __restrict__ sc_j, size_t sc_cap,
                                          size_t w_off) {
    int idx = (blockIdx.x - bid0) * blockDim.x + threadIdx.x;
    if (idx >= KANG * Q * Q) return;
    const int q2 = idx % Q;
    const int q1 = (idx / Q) % Q;
    const int k  = idx / (Q * Q);
    const size_t ang_off = (size_t)k * MM * MM;

    float2 acc[NIMG];
#pragma unroll
    for (int i = 0; i < NIMG; i++) acc[i] = make_float2(0.f, 0.f);
    const float invf2 = 1.0f / (float)(F * F);
    const float phc = PI_F * (float)(F - 1) / (float)MM;

    for (int r1 = 0; r1 < F; r1++) {
        const int k1 = q1 + Q * r1;
        const float c1 = cosf(PI_F * (float)k1 / (float)MM);
        const float ph1 = phc * (float)k1;
        for (int r2 = 0; r2 < F; r2++) {
            const int k2 = q2 + Q * r2;
            const size_t fidx = (size_t)k1 * MM + k2;
            const float s = (fidx < sc_cap) ? sc_j[fidx] : 0.0f;
            if (s == 0.0f) continue;
            const float a = (ang_off + fidx < ang_cap) ? ang[ang_off + fidx] : 0.0f;
            const float mg = s * a * invf2;
            if (mg == 0.0f) continue;
            const float c2 = cosf(PI_F * (float)k2 / (float)MM);
            float sp, cp;
            sincosf(ph1 + phc * (float)k2, &sp, &cp);
            const float m = mg * c1 * c2;
            const float2 wv = make_float2(m * cp, m * sp);
#pragma unroll
            for (int img = 0; img < NIMG; img++) {
                float2 xv = g_X[(size_t)img * (MM * MM) + fidx];
                acc[img].x += xv.x * wv.x - xv.y * wv.y;
                acc[img].y += xv.x * wv.y + xv.y * wv.x;
            }
        }
    }
#pragma unroll
    for (int img = 0; img < NIMG; img++) {
        size_t o = w_off + (((size_t)img * KANG + k) * Q + q1) * Q + q2;
        if (o < POOL_CAP) g_P[o] = acc[img];
    }
}

__device__ __forceinline__ void fold_low_body(const float* __restrict__ lp, size_t lp_cap,
                                              size_t w_off) {
    constexpr int F = 32, Q = 16;
    const int idx = threadIdx.x;
    const int q2 = idx & (Q - 1);
    const int q1 = idx >> 4;

    float2 acc[NIMG];
#pragma unroll
    for (int i = 0; i < NIMG; i++) acc[i] = make_float2(0.f, 0.f);
    const float invf2 = 1.0f / (float)(F * F);
    const float phc = PI_F * (float)(F - 1) / (float)MM;

    for (int r1 = 0; r1 < F; r1++) {
        const int k1 = q1 + Q * r1;
        const float c1 = cosf(PI_F * (float)k1 / (float)MM);
        const float ph1 = phc * (float)k1;
        for (int r2 = 0; r2 < F; r2++) {
            const int k2 = q2 + Q * r2;
            const size_t fidx = (size_t)k1 * MM + k2;
            const float s = (fidx < lp_cap) ? lp[fidx] : 0.0f;
            if (s == 0.0f) continue;
            const float c2 = cosf(PI_F * (float)k2 / (float)MM);
            float sp, cp;
            sincosf(ph1 + phc * (float)k2, &sp, &cp);
            const float m = s * invf2 * c1 * c2;
            const float2 wv = make_float2(m * cp, m * sp);
#pragma unroll
            for (int img = 0; img < NIMG; img++) {
                float2 xv = g_X[(size_t)img * (MM * MM) + fidx];
                acc[img].x += xv.x * wv.x - xv.y * wv.y;
                acc[img].y += xv.x * wv.y + xv.y * wv.x;
            }
        }
    }
#pragma unroll
    for (int img = 0; img < NIMG; img++) {
        size_t o = w_off + (size_t)img * (Q * Q) + q1 * Q + q2;
        if (o < POOL_CAP) g_P[o] = acc[img];
    }
}

__global__ void fold_all_kernel(const float* __restrict__ ang, size_t ang_cap,
                                const float* __restrict__ sc, size_t sc_cap,
                                const float* __restrict__ lp, size_t lp_cap) {
    const int b = blockIdx.x;
    const size_t scj = 262144u;
    if (b < 1024)
        fold_body(2, 256, 0, ang, ang_cap, sc, sc_cap, OFF_W0);
    else if (b < 1280)
        fold_body(4, 128, 1024, ang, ang_cap, sc + 1 * scj, sc_cap > 1 * scj ? sc_cap - 1 * scj : 0, OFF_W1);
    else if (b < 1344)
        fold_body(8, 64, 1280, ang, ang_cap, sc + 2 * scj, sc_cap > 2 * scj ? sc_cap - 2 * scj : 0, OFF_W2);
    else if (b < 1360)
        fold_body(16, 32, 1344, ang, ang_cap, sc + 3 * scj, sc_cap > 3 * scj ? sc_cap - 3 * scj : 0, OFF_W3);
    else if (b < 1364)
        fold_body(32, 16, 1360, ang, ang_cap, sc + 4 * scj, sc_cap > 4 * scj ? sc_cap - 4 * scj : 0, OFF_W4);
    else
        fold_low_body(lp, lp_cap, OFF_WL);
}

// ---------------------------------------------------------------------------
typedef int (*cuGetRange_t)(unsigned long long*, size_t*, unsigned long long);
static size_t dout_capacity_f(void* d_out, int out_size) {
    size_t bytes = 0;
    void* h = dlopen("libcuda.so.1", RTLD_NOW | RTLD_GLOBAL);
    if (!h) h = dlopen("libcuda.so", RTLD_NOW | RTLD_GLOBAL);
    if (h) {
        cuGetRange_t f = (cuGetRange_t)dlsym(h, "cuMemGetAddressRange_v2");
        if (!f) f = (cuGetRange_t)dlsym(h, "cuMemGetAddressRange");
        if (f) {
            unsigned long long base = 0; size_t sz = 0;
            if (f(&base, &sz, (unsigned long long)(uintptr_t)d_out) == 0 && sz > 0) {
                unsigned long long off = (unsigned long long)(uintptr_t)d_out - base;
                if (off < sz) bytes = sz - off;
            }
        }
    }
    if (bytes == 0) bytes = (size_t)out_size * 4u;
    size_t cap = bytes / 4u;
    if (cap > OUT_TOTAL) cap = OUT_TOTAL;
    return cap;
}

extern "C" void kernel_launch(void* const* d_in, const int* in_sizes, int n_in,
                              void* d_out, int out_size) {
    const float *x = nullptr, *hp = nullptr, *lp = nullptr, *ang = nullptr, *sc = nullptr;
    size_t xs = 0, hs = 0, ls = 0, as_ = 0, ss = 0;
    for (int i = 0; i < n_in; i++) {
        size_t s = (size_t)in_sizes[i];
        const float* p = (const float*)d_in[i];
        if (s == 3145728u && !x)        { x = p;  xs = s; }
        else if (s == 1048576u && !ang) { ang = p; as_ = s; }
        else if (s == 1310720u && !sc)  { sc = p; ss = s; }
        else if (s == 262144u) { if (!hp) { hp = p; hs = s; } else if (!lp) { lp = p; ls = s; } }
    }
    if (!x  && n_in > 0) { x  = (const float*)d_in[0]; xs  = (size_t)in_sizes[0]; }
    if (!hp && n_in > 1) { hp = (const float*)d_in[1]; hs  = (size_t)in_sizes[1]; }
    if (!lp && n_in > 2) { lp = (const float*)d_in[2]; ls  = (size_t)in_sizes[2]; }
    if (!ang&& n_in > 3) { ang= (const float*)d_in[3]; as_ = (size_t)in_sizes[3]; }
    if (!sc && n_in > 4) { sc = (const float*)d_in[4]; ss  = (size_t)in_sizes[4]; }

    float* outf = (float*)d_out;
    const size_t capf = dout_capacity_f(d_out, out_size);

    const int smFused = 2 * 64 * (64 + PADR) * 8;   // 67584
    cudaFuncSetAttribute(fused_all_kernel, cudaFuncAttributeMaxDynamicSharedMemorySize, smFused);

    const dim3 blk(256);

    // 1) forward FFT2 of x -> g_X  (R=16, L=512, 2 chunks -> 384 blocks)
    sfft_pass_kernel<16, 2, true , false><<<dim3(32, NIMG), blk>>>(
        x, xs, 0, 0, nullptr, 0, 0, 1, OFF_FT, nullptr, 0, -1, 1.0f);
    sfft_pass_kernel<16, 2, false, false><<<dim3(32, NIMG), blk>>>(
        nullptr, 0, 1, OFF_FT, nullptr, 0, 0, 0, 0, nullptr, 0, -1, 1.0f);

    // 2) highpass -> out0
    sfft_pass_kernel<16, 2, false, false><<<dim3(32, NIMG), blk>>>(
        nullptr, 0, 0, 0, nullptr, 0, 0, 1, OFF_FT, hp, hs, +1, 1.0f);
    sfft_pass_kernel<16, 2, false, true ><<<dim3(32, NIMG), blk>>>(
        nullptr, 0, 1, OFF_FT, outf, 0, capf, 0, 0, nullptr, 0, +1, 1.0f / 262144.0f);

    // 3) all folds in one launch
    fold_all_kernel<<<1365, blk>>>(ang, as_, sc, ss, lp, ls);

    // 4) j0 (Q=256, R=8, 4 chunks -> 384 blocks) -> out1
    sfft_pass_kernel<8, 4, false, false><<<dim3(8, 48), blk>>>(
        nullptr, 0, 1, OFF_W0, nullptr, 0, 0, 1, OFF_T0, nullptr, 0, +1, 1.0f);
    sfft_pass_kernel<8, 4, false, true ><<<dim3(8, 48), blk>>>(
        nullptr, 0, 1, OFF_T0, outf, 3145728, capf, 0, 0, nullptr, 0, +1, 1.0f / 65536.0f);

    // 5) j1 (Q=128, R=4, 2 chunks -> 384 blocks) -> out2
    sfft_pass_kernel<4, 2, false, false><<<dim3(8, 48), blk>>>(
        nullptr, 0, 1, OFF_W1, nullptr, 0, 0, 1, OFF_T1, nullptr, 0, +1, 1.0f);
    sfft_pass_kernel<4, 2, false, true ><<<dim3(8, 48), blk>>>(
        nullptr, 0, 1, OFF_T1, outf, 6291456, capf, 0, 0, nullptr, 0, +1, 1.0f / 16384.0f);

    // 6) all fused small bands in one launch
    fused_all_kernel<<<156, blk, smFused>>>(outf, capf);
}